// round 1
// baseline (speedup 1.0000x reference)
#include <cuda_runtime.h>
#include <math.h>

// ---------------------------------------------------------------------------
// Problem constants
// ---------------------------------------------------------------------------
#define BB 256
#define TT 64
#define LL 1024
#define SS 512
#define NCLS 239
#define MBT (BB * TT)          // 16384

// ---------------------------------------------------------------------------
// Scratch (device globals; no runtime allocation allowed)
// ---------------------------------------------------------------------------
__device__ float g_feats [MBT * 2048];   // proj-MLP output           [B*T, 2048]
__device__ float g_sfeats[MBT * 512];    // small-proj output         [B*T, 512]
__device__ float g_sgpre [MBT * 2048];   // small LSTM input gates    [B*T, 4S]
__device__ float g_lgpre [MBT * 4096];   // large LSTM input gates    [B*T, 4L]
__device__ float g_Gs[BB * 2048];        // per-step small gates
__device__ float g_Gl[BB * 4096];        // per-step large gates
__device__ float g_hl[2][BB * LL];
__device__ float g_cl[2][BB * LL];
__device__ float g_hs[2][BB * SS];
__device__ float g_cs[2][BB * SS];

// ---------------------------------------------------------------------------
// Generic tiled GEMM:  C[M,N] = epi( A[M,K] @ W[N,K]^T + b1 + b2 + addsrc )
//   A row-major with leading dim lda, W row-major (PyTorch weight layout) ldw.
//   addsrc indexed addsrc[m*ldadd + n] (lets us read strided precomputed gates).
//   epi: 0 = none, 1 = BatchNorm(inference, mean=0,var=1) + ReLU.
//   Requires: M % BM == 0, K % 16 == 0 (true for all call sites). N guarded.
// ---------------------------------------------------------------------------
template<int BM, int BN, int TM, int TN>
__global__ __launch_bounds__((BM/TM)*(BN/TN))
void gemm_kernel(const float* __restrict__ A, int lda,
                 const float* __restrict__ W, int ldw,
                 const float* __restrict__ b1, const float* __restrict__ b2,
                 const float* __restrict__ addsrc, int ldadd,
                 float* __restrict__ C, int ldc,
                 int M, int N, int K, int epi,
                 const float* __restrict__ gamma, const float* __restrict__ beta)
{
    constexpr int BK = 16;
    constexpr int TX = BN / TN;
    constexpr int TY = BM / TM;
    constexpr int NT = TX * TY;
    constexpr int AV = (BM * BK / 4) / NT;   // float4 loads per thread (A tile)
    constexpr int WV = (BN * BK / 4) / NT;   // float4 loads per thread (W tile)

    __shared__ float As[BK][BM + 4];
    __shared__ float Ws[BK][BN + 4];

    const int tid = threadIdx.x;
    const int bm  = blockIdx.y * BM;
    const int bn  = blockIdx.x * BN;
    const int tx  = tid % TX;
    const int ty  = tid / TX;

    float acc[TM][TN];
#pragma unroll
    for (int i = 0; i < TM; i++)
#pragma unroll
        for (int j = 0; j < TN; j++) acc[i][j] = 0.f;

    for (int k0 = 0; k0 < K; k0 += BK) {
        // ---- load A tile (BM x BK), transposed into As[k][m]
#pragma unroll
        for (int v = 0; v < AV; v++) {
            int vid = tid + v * NT;
            int row = vid >> 2;
            int kc  = (vid & 3) * 4;
            float4 x = *reinterpret_cast<const float4*>(
                &A[(size_t)(bm + row) * lda + k0 + kc]);
            As[kc + 0][row] = x.x; As[kc + 1][row] = x.y;
            As[kc + 2][row] = x.z; As[kc + 3][row] = x.w;
        }
        // ---- load W tile (BN x BK), transposed into Ws[k][n]
#pragma unroll
        for (int v = 0; v < WV; v++) {
            int vid = tid + v * NT;
            int row = vid >> 2;
            int kc  = (vid & 3) * 4;
            float4 x = make_float4(0.f, 0.f, 0.f, 0.f);
            if (bn + row < N)
                x = *reinterpret_cast<const float4*>(
                    &W[(size_t)(bn + row) * ldw + k0 + kc]);
            Ws[kc + 0][row] = x.x; Ws[kc + 1][row] = x.y;
            Ws[kc + 2][row] = x.z; Ws[kc + 3][row] = x.w;
        }
        __syncthreads();

#pragma unroll
        for (int kk = 0; kk < BK; kk++) {
            float a[TM], w[TN];
#pragma unroll
            for (int i = 0; i < TM / 4; i++) {
                float4 x = *reinterpret_cast<const float4*>(&As[kk][ty * TM + i * 4]);
                a[i*4] = x.x; a[i*4+1] = x.y; a[i*4+2] = x.z; a[i*4+3] = x.w;
            }
#pragma unroll
            for (int j = 0; j < TN / 4; j++) {
                float4 x = *reinterpret_cast<const float4*>(&Ws[kk][tx * TN + j * 4]);
                w[j*4] = x.x; w[j*4+1] = x.y; w[j*4+2] = x.z; w[j*4+3] = x.w;
            }
#pragma unroll
            for (int i = 0; i < TM; i++)
#pragma unroll
                for (int j = 0; j < TN; j++) acc[i][j] = fmaf(a[i], w[j], acc[i][j]);
        }
        __syncthreads();
    }

    // ---- epilogue
    const float inv_std = rsqrtf(1.0f + 1e-5f);
#pragma unroll
    for (int i = 0; i < TM; i++) {
        int m = bm + ty * TM + i;
#pragma unroll
        for (int j = 0; j < TN; j++) {
            int n = bn + tx * TN + j;
            if (n < N) {
                float v = acc[i][j];
                if (b1) v += b1[n];
                if (b2) v += b2[n];
                if (addsrc) v += addsrc[(size_t)m * ldadd + n];
                if (epi == 1)
                    v = fmaxf(0.f, v * (gamma[n] * inv_std) + beta[n]);
                C[(size_t)m * ldc + n] = v;
            }
        }
    }
}

// ---------------------------------------------------------------------------
// Elementwise / tiny kernels
// ---------------------------------------------------------------------------
__device__ __forceinline__ float sigf(float x) { return 1.f / (1.f + expf(-x)); }

__global__ void zero_states_kernel(float* hl, float* cl, float* hs, float* cs)
{
    int i = blockIdx.x * blockDim.x + threadIdx.x;
    if (i < BB * LL) { hl[i] = 0.f; cl[i] = 0.f; }
    if (i < BB * SS) { hs[i] = 0.f; cs[i] = 0.f; }
}

// small LSTM activation: gates G [B, 4S] already include input-part + biases
__global__ void small_act_kernel(const float* __restrict__ G,
                                 const float* __restrict__ c_old,
                                 float* __restrict__ h_new, float* __restrict__ c_new)
{
    int idx = blockIdx.x * blockDim.x + threadIdx.x;
    if (idx >= BB * SS) return;
    int b = idx >> 9, n = idx & (SS - 1);
    const float* g = G + (size_t)b * (4 * SS);
    float i_ = sigf(g[n]);
    float f_ = sigf(g[SS + n]);
    float gg = tanhf(g[2 * SS + n]);
    float o_ = sigf(g[3 * SS + n]);
    float c2 = f_ * c_old[idx] + i_ * gg;
    c_new[idx] = c2;
    h_new[idx] = o_ * tanhf(c2);
}

// gate: p = [s_t, h_l, c_l] @ W_g^T + b_g ; r = one_hot(argmax(p)).
// (straight-through forward value is exactly the hard one-hot; TAU=1 softmax
//  of a log_softmax preserves argmax, so no exp needed.)
__global__ void gate_kernel(const float* __restrict__ sfeats, int t,
                            const float* __restrict__ h_l, const float* __restrict__ c_l,
                            const float* __restrict__ W_g, const float* __restrict__ b_g,
                            float* __restrict__ r_out /* [B,2] slice of d_out */)
{
    const int b = blockIdx.x;
    const int tid = threadIdx.x;                       // 256 threads
    const float* s = sfeats + ((size_t)b * TT + t) * SS;
    const float* h = h_l + (size_t)b * LL;
    const float* c = c_l + (size_t)b * LL;
    const float* w0 = W_g;           // row 0, 2560 cols
    const float* w1 = W_g + 2560;    // row 1

    float p0 = 0.f, p1 = 0.f;
    for (int j = tid; j < SS; j += 256) {
        float v = s[j]; p0 += v * w0[j]; p1 += v * w1[j];
    }
    for (int j = tid; j < LL; j += 256) {
        float v = h[j]; p0 += v * w0[SS + j]; p1 += v * w1[SS + j];
    }
    for (int j = tid; j < LL; j += 256) {
        float v = c[j]; p0 += v * w0[SS + LL + j]; p1 += v * w1[SS + LL + j];
    }
    __shared__ float s0[256], s1[256];
    s0[tid] = p0; s1[tid] = p1;
    __syncthreads();
    for (int st = 128; st > 0; st >>= 1) {
        if (tid < st) { s0[tid] += s0[tid + st]; s1[tid] += s1[tid + st]; }
        __syncthreads();
    }
    if (tid == 0) {
        float a = s0[0] + b_g[0];
        float d = s1[0] + b_g[1];
        float r0 = (a >= d) ? 1.f : 0.f;   // jnp.argmax: first index wins ties
        r_out[b * 2 + 0] = r0;
        r_out[b * 2 + 1] = 1.f - r0;
    }
}

// large LSTM activation + straight-through merge with the skip (partial) state
__global__ void large_act_merge_kernel(const float* __restrict__ G,
                                       const float* __restrict__ h_old,
                                       const float* __restrict__ c_old,
                                       const float* __restrict__ h_s_new,
                                       const float* __restrict__ c_s_new,
                                       const float* __restrict__ r,  // [B,2]
                                       float* __restrict__ h_new,
                                       float* __restrict__ c_new)
{
    int idx = blockIdx.x * blockDim.x + threadIdx.x;
    if (idx >= BB * LL) return;
    int b = idx >> 10, n = idx & (LL - 1);
    const float* g = G + (size_t)b * (4 * LL);
    float i_ = sigf(g[n]);
    float f_ = sigf(g[LL + n]);
    float gg = tanhf(g[2 * LL + n]);
    float o_ = sigf(g[3 * LL + n]);
    float c_ln = f_ * c_old[idx] + i_ * gg;
    float h_ln = o_ * tanhf(c_ln);
    float ph = (n < SS) ? h_s_new[b * SS + n] : h_old[idx];
    float pc = (n < SS) ? c_s_new[b * SS + n] : c_old[idx];
    float r0 = r[b * 2], r1 = r[b * 2 + 1];
    h_new[idx] = r0 * h_ln + r1 * ph;
    c_new[idx] = r0 * c_ln + r1 * pc;
}

// ---------------------------------------------------------------------------
// Launch
// ---------------------------------------------------------------------------
static inline float* symaddr(const void* sym)
{
    void* p = nullptr;
    cudaGetSymbolAddress(&p, sym);
    return (float*)p;
}

extern "C" void kernel_launch(void* const* d_in, const int* in_sizes, int n_in,
                              void* d_out, int out_size)
{
    const float* x      = (const float*)d_in[0];
    const float* xs     = (const float*)d_in[1];
    const float* W_p    = (const float*)d_in[2];
    const float* b_p    = (const float*)d_in[3];
    const float* g_p    = (const float*)d_in[4];
    const float* be_p   = (const float*)d_in[5];
    const float* W_s    = (const float*)d_in[6];
    const float* b_s    = (const float*)d_in[7];
    const float* g_s    = (const float*)d_in[8];
    const float* be_s   = (const float*)d_in[9];
    const float* Wih_l  = (const float*)d_in[10];
    const float* Whh_l  = (const float*)d_in[11];
    const float* bih_l  = (const float*)d_in[12];
    const float* bhh_l  = (const float*)d_in[13];
    const float* Wih_s  = (const float*)d_in[14];
    const float* Whh_s  = (const float*)d_in[15];
    const float* bih_s  = (const float*)d_in[16];
    const float* bhh_s  = (const float*)d_in[17];
    const float* W_g    = (const float*)d_in[18];
    const float* b_g    = (const float*)d_in[19];
    const float* W_c    = (const float*)d_in[20];
    const float* b_c    = (const float*)d_in[21];

    float* out = (float*)d_out;
    float* out_logits = out;                       // [B, NC]
    float* out_r      = out + BB * NCLS;           // [T, B, 2]

    float* feats  = symaddr(g_feats);
    float* sfeats = symaddr(g_sfeats);
    float* sgpre  = symaddr(g_sgpre);
    float* lgpre  = symaddr(g_lgpre);
    float* Gs     = symaddr(g_Gs);
    float* Gl     = symaddr(g_Gl);
    float* hl     = symaddr(g_hl);   // [2][B*L] contiguous
    float* cl     = symaddr(g_cl);
    float* hs     = symaddr(g_hs);
    float* cs     = symaddr(g_cs);

    // zero initial states (buffer 0)
    zero_states_kernel<<<(BB * LL + 255) / 256, 256>>>(hl, cl, hs, cs);

    // ---- Phase 1: time-parallel GEMMs (all frames at once) ----
    // feats = relu(BN(x @ W_p^T + b_p))
    gemm_kernel<128,128,8,8><<<dim3(2048/128, MBT/128), 256>>>(
        x, 2048, W_p, 2048, b_p, nullptr, nullptr, 0,
        feats, 2048, MBT, 2048, 2048, 1, g_p, be_p);
    // sfeats = relu(BN(x_small @ W_s^T + b_s))
    gemm_kernel<128,128,8,8><<<dim3(512/128, MBT/128), 256>>>(
        xs, 1280, W_s, 1280, b_s, nullptr, nullptr, 0,
        sfeats, 512, MBT, 512, 1280, 1, g_s, be_s);
    // sg_pre = sfeats @ Wih_s^T + bih_s + bhh_s
    gemm_kernel<128,128,8,8><<<dim3(2048/128, MBT/128), 256>>>(
        sfeats, 512, Wih_s, 512, bih_s, bhh_s, nullptr, 0,
        sgpre, 2048, MBT, 2048, 512, 0, nullptr, nullptr);
    // lg_pre = feats @ Wih_l[:, :2048]^T + bih_l + bhh_l
    gemm_kernel<128,128,8,8><<<dim3(4096/128, MBT/128), 256>>>(
        feats, 2048, Wih_l, 2560, bih_l, bhh_l, nullptr, 0,
        lgpre, 4096, MBT, 4096, 2048, 0, nullptr, nullptr);
    // lg_pre += sfeats @ Wih_l[:, 2048:2560]^T
    gemm_kernel<128,128,8,8><<<dim3(4096/128, MBT/128), 256>>>(
        sfeats, 512, Wih_l + 2048, 2560, nullptr, nullptr, lgpre, 4096,
        lgpre, 4096, MBT, 4096, 512, 0, nullptr, nullptr);

    // ---- Phase 2: recurrence over T steps ----
    for (int t = 0; t < TT; t++) {
        int cur = t & 1, nxt = 1 - cur;
        float* hl_c = hl + (size_t)cur * BB * LL;
        float* cl_c = cl + (size_t)cur * BB * LL;
        float* hl_n = hl + (size_t)nxt * BB * LL;
        float* cl_n = cl + (size_t)nxt * BB * LL;
        float* hs_c = hs + (size_t)cur * BB * SS;
        float* cs_c = cs + (size_t)cur * BB * SS;
        float* hs_n = hs + (size_t)nxt * BB * SS;
        float* cs_n = cs + (size_t)nxt * BB * SS;
        float* r_t  = out_r + (size_t)t * BB * 2;

        // small gates: Gs = sg_pre[:,t,:] + h_s @ Whh_s^T
        gemm_kernel<64,64,4,4><<<dim3(2048/64, BB/64), 256>>>(
            hs_c, 512, Whh_s, 512, nullptr, nullptr,
            sgpre + (size_t)t * 2048, TT * 2048,
            Gs, 2048, BB, 2048, 512, 0, nullptr, nullptr);
        small_act_kernel<<<(BB * SS + 255) / 256, 256>>>(Gs, cs_c, hs_n, cs_n);

        // hard gate on OLD large state
        gate_kernel<<<BB, 256>>>(sfeats, t, hl_c, cl_c, W_g, b_g, r_t);

        // large gates: Gl = lg_pre[:,t,:] + h_l @ Whh_l^T
        gemm_kernel<64,64,4,4><<<dim3(4096/64, BB/64), 256>>>(
            hl_c, 1024, Whh_l, 1024, nullptr, nullptr,
            lgpre + (size_t)t * 4096, TT * 4096,
            Gl, 4096, BB, 4096, 1024, 0, nullptr, nullptr);
        large_act_merge_kernel<<<(BB * LL + 255) / 256, 256>>>(
            Gl, hl_c, cl_c, hs_n, cs_n, r_t, hl_n, cl_n);
    }

    // ---- classifier: logits = h_l_final @ W_c^T + b_c  (final state in buf 0)
    gemm_kernel<64,64,4,4><<<dim3((NCLS + 63) / 64, BB / 64), 256>>>(
        hl + (size_t)(TT & 1) * BB * LL, 1024, W_c, 1024, b_c, nullptr, nullptr, 0,
        out_logits, NCLS, BB, NCLS, 1024, 0, nullptr, nullptr);
}

// round 2
// speedup vs baseline: 1.3757x; 1.3757x over previous
#include <cuda_runtime.h>
#include <cuda_bf16.h>
#include <math.h>
#include <stdint.h>

// ---------------------------------------------------------------------------
// Problem constants
// ---------------------------------------------------------------------------
#define BB 256
#define TT 64
#define LL 1024
#define SS 512
#define NCLS 239
#define MBT (BB * TT)          // 16384

typedef __nv_bfloat16 bf16;

// ---------------------------------------------------------------------------
// Scratch (device globals; no runtime allocation allowed)
// ---------------------------------------------------------------------------
// bf16 split pairs of inputs / activations
__device__ bf16 g_x_hi  [MBT * 2048];
__device__ bf16 g_x_lo  [MBT * 2048];
__device__ bf16 g_xs_hi [MBT * 1280];
__device__ bf16 g_xs_lo [MBT * 1280];
__device__ bf16 g_f_hi  [MBT * 2048];   // feats split
__device__ bf16 g_f_lo  [MBT * 2048];
__device__ bf16 g_sf_hi [MBT * 512];    // sfeats split
__device__ bf16 g_sf_lo [MBT * 512];
// bf16 split pairs of weights
__device__ bf16 g_Wp_hi [2048 * 2048];
__device__ bf16 g_Wp_lo [2048 * 2048];
__device__ bf16 g_Ws_hi [512 * 1280];
__device__ bf16 g_Ws_lo [512 * 1280];
__device__ bf16 g_Wlm_hi[4096 * 2048];  // Wih_l[:, :2048]
__device__ bf16 g_Wlm_lo[4096 * 2048];
__device__ bf16 g_Wls_hi[4096 * 512];   // Wih_l[:, 2048:2560]
__device__ bf16 g_Wls_lo[4096 * 512];
__device__ bf16 g_Whl_hi[4096 * 1024];  // Whh_l
__device__ bf16 g_Whl_lo[4096 * 1024];
__device__ bf16 g_Wis_hi[2048 * 512];   // Wih_s
__device__ bf16 g_Wis_lo[2048 * 512];
__device__ bf16 g_Whs_hi[2048 * 512];   // Whh_s
__device__ bf16 g_Whs_lo[2048 * 512];
__device__ bf16 g_Wc_hi [NCLS * 1024];
__device__ bf16 g_Wc_lo [NCLS * 1024];
// fp32 scratch
__device__ float g_sfeats[MBT * 512];
__device__ float g_sgpre [MBT * 2048];
__device__ float g_lgpre [MBT * 4096];
__device__ float g_Gs[BB * 2048];
__device__ float g_Gl[BB * 4096];
__device__ float g_hl[2][BB * LL];
__device__ float g_cl[2][BB * LL];
__device__ float g_hs[2][BB * SS];
__device__ float g_cs[2][BB * SS];
// bf16 splits of recurrent states (GEMM A operands)
__device__ bf16 g_hl_hi[2][BB * LL];
__device__ bf16 g_hl_lo[2][BB * LL];
__device__ bf16 g_hs_hi[2][BB * SS];
__device__ bf16 g_hs_lo[2][BB * SS];

// ---------------------------------------------------------------------------
// PTX helpers
// ---------------------------------------------------------------------------
__device__ __forceinline__ uint32_t smem_u32(const void* p) {
    return (uint32_t)__cvta_generic_to_shared(p);
}
__device__ __forceinline__ void cp16(uint32_t dst, const void* src, int srcsize) {
    asm volatile("cp.async.cg.shared.global [%0], [%1], 16, %2;\n"
                 :: "r"(dst), "l"(src), "r"(srcsize));
}
__device__ __forceinline__ void cp_commit() {
    asm volatile("cp.async.commit_group;\n");
}
template<int N>
__device__ __forceinline__ void cp_wait() {
    asm volatile("cp.async.wait_group %0;\n" :: "n"(N));
}
__device__ __forceinline__ void ldsm4(uint32_t* r, uint32_t addr) {
    asm volatile("ldmatrix.sync.aligned.m8n8.x4.shared.b16 {%0,%1,%2,%3}, [%4];\n"
                 : "=r"(r[0]), "=r"(r[1]), "=r"(r[2]), "=r"(r[3]) : "r"(addr));
}
__device__ __forceinline__ void mma_bf16(float* d, const uint32_t* a, uint32_t b0, uint32_t b1) {
    asm volatile("mma.sync.aligned.m16n8k16.row.col.f32.bf16.bf16.f32 "
                 "{%0,%1,%2,%3},{%4,%5,%6,%7},{%8,%9},{%0,%1,%2,%3};\n"
                 : "+f"(d[0]), "+f"(d[1]), "+f"(d[2]), "+f"(d[3])
                 : "r"(a[0]), "r"(a[1]), "r"(a[2]), "r"(a[3]), "r"(b0), "r"(b1));
}

// ---------------------------------------------------------------------------
// Split-bf16 triple-product GEMM:
//   C[M,N] = epi( A@W^T ) where A = A_hi + A_lo, W = W_hi + W_lo (fp32-accurate)
//   computed as A_hi·W_hi + A_hi·W_lo + A_lo·W_hi on tensor cores.
//   A row-major [M,K] (lda), W row-major [N,K] (ldb, PyTorch layout).
//   Epilogue (all runtime-nullable): +b1[n], +b2[n], +addsrc[m*ldadd+n],
//   BN-ReLU (gamma,beta), accumulate into Cf, write Cf fp32, write Chi/Clo split.
//   Requires M % BM == 0, K % 32 == 0.
// ---------------------------------------------------------------------------
template<int BM, int BN>
__global__ void __launch_bounds__((BM/64)*(BN/32)*32)
gemm3_kernel(const bf16* __restrict__ Ahi, const bf16* __restrict__ Alo, int lda,
             const bf16* __restrict__ Bhi, const bf16* __restrict__ Blo, int ldb,
             int M, int N, int K,
             const float* __restrict__ b1, const float* __restrict__ b2,
             const float* __restrict__ addsrc, int ldadd,
             const float* __restrict__ gamma, const float* __restrict__ beta,
             float* __restrict__ Cf, int ldc, int accum,
             bf16* __restrict__ Chi, bf16* __restrict__ Clo, int ldsp)
{
    constexpr int WGN = BN / 32;
    constexpr int WGM = BM / 64;
    constexpr int NT  = WGM * WGN * 32;
    constexpr int LDS = 40;                       // halves per smem row (padded)

    __shared__ bf16 As[2][BM * LDS];
    __shared__ bf16 Bs[2][BN * LDS];

    const int tid  = threadIdx.x;
    const int lane = tid & 31;
    const int wid  = tid >> 5;
    const int wm   = wid / WGN;
    const int wn   = wid % WGN;
    const int bm   = blockIdx.y * BM;
    const int bn   = blockIdx.x * BN;

    const uint32_t asb[2] = { smem_u32(As[0]), smem_u32(As[1]) };
    const uint32_t bsb[2] = { smem_u32(Bs[0]), smem_u32(Bs[1]) };

    const int NK  = K / 32;
    const int NIT = 3 * NK;

    float acc[4][4][4];
#pragma unroll
    for (int i = 0; i < 4; i++)
#pragma unroll
        for (int j = 0; j < 4; j++)
#pragma unroll
            for (int r = 0; r < 4; r++) acc[i][j][r] = 0.f;

    auto stage = [&](int buf, int it) {
        int p  = it / NK;
        int kt = it - p * NK;
        int k0 = kt * 32;
        const bf16* Ap = (p == 2) ? Alo : Ahi;
        const bf16* Bp = (p == 1) ? Blo : Bhi;
#pragma unroll 2
        for (int v = tid; v < BM * 4; v += NT) {
            int row = v >> 2, kc = (v & 3) * 8;
            cp16(asb[buf] + (row * LDS + kc) * 2,
                 Ap + (size_t)(bm + row) * lda + k0 + kc, 16);
        }
#pragma unroll 2
        for (int v = tid; v < BN * 4; v += NT) {
            int row = v >> 2, kc = (v & 3) * 8;
            int n = bn + row;
            bool ok = (n < N);
            cp16(bsb[buf] + (row * LDS + kc) * 2,
                 Bp + (size_t)(ok ? n : 0) * ldb + k0 + kc, ok ? 16 : 0);
        }
    };

    stage(0, 0);
    cp_commit();

    for (int it = 0; it < NIT; it++) {
        int cur = it & 1;
        if (it + 1 < NIT) { stage(cur ^ 1, it + 1); cp_commit(); cp_wait<1>(); }
        else              { cp_wait<0>(); }
        __syncthreads();

#pragma unroll
        for (int ks = 0; ks < 32; ks += 16) {
            uint32_t a[4][4], b[4][2];
#pragma unroll
            for (int mi = 0; mi < 4; mi++) {
                int row = wm * 64 + mi * 16 + (lane & 15);
                int kk  = ks + (lane >> 4) * 8;
                ldsm4(a[mi], asb[cur] + (row * LDS + kk) * 2);
            }
#pragma unroll
            for (int ng = 0; ng < 2; ng++) {
                int row = wn * 32 + ng * 16 + (lane & 7) + ((lane >> 4) << 3);
                int kk  = ks + (((lane >> 3) & 1) << 3);
                uint32_t t[4];
                ldsm4(t, bsb[cur] + (row * LDS + kk) * 2);
                b[2 * ng][0] = t[0]; b[2 * ng][1] = t[1];
                b[2 * ng + 1][0] = t[2]; b[2 * ng + 1][1] = t[3];
            }
#pragma unroll
            for (int mi = 0; mi < 4; mi++)
#pragma unroll
                for (int nj = 0; nj < 4; nj++)
                    mma_bf16(acc[mi][nj], a[mi], b[nj][0], b[nj][1]);
        }
        __syncthreads();
    }

    // ---- epilogue
    const float inv_std = rsqrtf(1.0f + 1e-5f);
    const int g  = lane >> 2;
    const int tg = lane & 3;
#pragma unroll
    for (int mi = 0; mi < 4; mi++)
#pragma unroll
        for (int nj = 0; nj < 4; nj++)
#pragma unroll
            for (int r = 0; r < 4; r++) {
                int m = bm + wm * 64 + mi * 16 + g + ((r >> 1) << 3);
                int n = bn + wn * 32 + nj * 8 + tg * 2 + (r & 1);
                if (n >= N) continue;
                float v = acc[mi][nj][r];
                if (b1)     v += b1[n];
                if (b2)     v += b2[n];
                if (addsrc) v += addsrc[(size_t)m * ldadd + n];
                if (gamma)  v = fmaxf(0.f, v * (gamma[n] * inv_std) + beta[n]);
                if (accum)  v += Cf[(size_t)m * ldc + n];
                if (Cf)     Cf[(size_t)m * ldc + n] = v;
                if (Chi) {
                    bf16 h = __float2bfloat16(v);
                    Chi[(size_t)m * ldsp + n] = h;
                    Clo[(size_t)m * ldsp + n] = __float2bfloat16(v - __bfloat162float(h));
                }
            }
}

// ---------------------------------------------------------------------------
// Elementwise kernels
// ---------------------------------------------------------------------------
__device__ __forceinline__ float sigf(float x) { return 1.f / (1.f + expf(-x)); }
__device__ __forceinline__ void split1(float v, bf16* hi, bf16* lo, size_t i) {
    bf16 h = __float2bfloat16(v);
    hi[i] = h;
    lo[i] = __float2bfloat16(v - __bfloat162float(h));
}

// contiguous fp32 -> bf16 hi/lo
__global__ void split_kernel(const float* __restrict__ src, bf16* hi, bf16* lo, int n)
{
    int i = blockIdx.x * blockDim.x + threadIdx.x;
    if (i < n) split1(src[i], hi, lo, i);
}

// strided (sub-matrix) fp32 -> bf16 hi/lo, dst is dense [rows, cols]
__global__ void splitw_kernel(const float* __restrict__ src, int src_ld, int col0,
                              bf16* hi, bf16* lo, int rows, int cols)
{
    int i = blockIdx.x * blockDim.x + threadIdx.x;
    if (i >= rows * cols) return;
    int r = i / cols, c = i - r * cols;
    split1(src[(size_t)r * src_ld + col0 + c], hi, lo, i);
}

__global__ void zero_states_kernel(float* hl, float* cl, float* hs, float* cs,
                                   bf16* hlh, bf16* hll, bf16* hsh, bf16* hsl)
{
    int i = blockIdx.x * blockDim.x + threadIdx.x;
    if (i < BB * LL) { hl[i] = 0.f; cl[i] = 0.f; hlh[i] = __float2bfloat16(0.f); hll[i] = __float2bfloat16(0.f); }
    if (i < BB * SS) { hs[i] = 0.f; cs[i] = 0.f; hsh[i] = __float2bfloat16(0.f); hsl[i] = __float2bfloat16(0.f); }
}

__global__ void small_act_kernel(const float* __restrict__ G,
                                 const float* __restrict__ c_old,
                                 float* __restrict__ h_new, float* __restrict__ c_new,
                                 bf16* __restrict__ hh, bf16* __restrict__ hl)
{
    int idx = blockIdx.x * blockDim.x + threadIdx.x;
    if (idx >= BB * SS) return;
    int b = idx >> 9, n = idx & (SS - 1);
    const float* g = G + (size_t)b * (4 * SS);
    float i_ = sigf(g[n]);
    float f_ = sigf(g[SS + n]);
    float gg = tanhf(g[2 * SS + n]);
    float o_ = sigf(g[3 * SS + n]);
    float c2 = f_ * c_old[idx] + i_ * gg;
    float h2 = o_ * tanhf(c2);
    c_new[idx] = c2;
    h_new[idx] = h2;
    split1(h2, hh, hl, idx);
}

// hard straight-through gate: r = one_hot(argmax([s_t,h_l,c_l] @ W_g^T + b_g))
__global__ void gate_kernel(const float* __restrict__ sfeats, int t,
                            const float* __restrict__ h_l, const float* __restrict__ c_l,
                            const float* __restrict__ W_g, const float* __restrict__ b_g,
                            float* __restrict__ r_out)
{
    const int b = blockIdx.x;
    const int tid = threadIdx.x;
    const float* s = sfeats + ((size_t)b * TT + t) * SS;
    const float* h = h_l + (size_t)b * LL;
    const float* c = c_l + (size_t)b * LL;
    const float* w0 = W_g;
    const float* w1 = W_g + 2560;

    float p0 = 0.f, p1 = 0.f;
    for (int j = tid; j < SS; j += 256) { float v = s[j]; p0 += v * w0[j]; p1 += v * w1[j]; }
    for (int j = tid; j < LL; j += 256) { float v = h[j]; p0 += v * w0[SS + j]; p1 += v * w1[SS + j]; }
    for (int j = tid; j < LL; j += 256) { float v = c[j]; p0 += v * w0[SS + LL + j]; p1 += v * w1[SS + LL + j]; }
    __shared__ float s0[256], s1[256];
    s0[tid] = p0; s1[tid] = p1;
    __syncthreads();
    for (int st = 128; st > 0; st >>= 1) {
        if (tid < st) { s0[tid] += s0[tid + st]; s1[tid] += s1[tid + st]; }
        __syncthreads();
    }
    if (tid == 0) {
        float r0 = (s0[0] + b_g[0] >= s1[0] + b_g[1]) ? 1.f : 0.f;
        r_out[b * 2 + 0] = r0;
        r_out[b * 2 + 1] = 1.f - r0;
    }
}

__global__ void large_act_merge_kernel(const float* __restrict__ G,
                                       const float* __restrict__ h_old,
                                       const float* __restrict__ c_old,
                                       const float* __restrict__ h_s_new,
                                       const float* __restrict__ c_s_new,
                                       const float* __restrict__ r,
                                       float* __restrict__ h_new,
                                       float* __restrict__ c_new,
                                       bf16* __restrict__ hh, bf16* __restrict__ hl)
{
    int idx = blockIdx.x * blockDim.x + threadIdx.x;
    if (idx >= BB * LL) return;
    int b = idx >> 10, n = idx & (LL - 1);
    const float* g = G + (size_t)b * (4 * LL);
    float i_ = sigf(g[n]);
    float f_ = sigf(g[LL + n]);
    float gg = tanhf(g[2 * LL + n]);
    float o_ = sigf(g[3 * LL + n]);
    float c_ln = f_ * c_old[idx] + i_ * gg;
    float h_ln = o_ * tanhf(c_ln);
    float ph = (n < SS) ? h_s_new[b * SS + n] : h_old[idx];
    float pc = (n < SS) ? c_s_new[b * SS + n] : c_old[idx];
    float r0 = r[b * 2], r1 = r[b * 2 + 1];
    float h2 = r0 * h_ln + r1 * ph;
    c_new[idx] = r0 * c_ln + r1 * pc;
    h_new[idx] = h2;
    split1(h2, hh, hl, idx);
}

// ---------------------------------------------------------------------------
// Launch
// ---------------------------------------------------------------------------
static inline float* fsym(const void* s) { void* p = nullptr; cudaGetSymbolAddress(&p, s); return (float*)p; }
static inline bf16*  bsym(const void* s) { void* p = nullptr; cudaGetSymbolAddress(&p, s); return (bf16*)p; }

extern "C" void kernel_launch(void* const* d_in, const int* in_sizes, int n_in,
                              void* d_out, int out_size)
{
    const float* x     = (const float*)d_in[0];
    const float* xs    = (const float*)d_in[1];
    const float* W_p   = (const float*)d_in[2];
    const float* b_p   = (const float*)d_in[3];
    const float* g_p   = (const float*)d_in[4];
    const float* be_p  = (const float*)d_in[5];
    const float* W_s   = (const float*)d_in[6];
    const float* b_s   = (const float*)d_in[7];
    const float* g_s   = (const float*)d_in[8];
    const float* be_s  = (const float*)d_in[9];
    const float* Wih_l = (const float*)d_in[10];
    const float* Whh_l = (const float*)d_in[11];
    const float* bih_l = (const float*)d_in[12];
    const float* bhh_l = (const float*)d_in[13];
    const float* Wih_s = (const float*)d_in[14];
    const float* Whh_s = (const float*)d_in[15];
    const float* bih_s = (const float*)d_in[16];
    const float* bhh_s = (const float*)d_in[17];
    const float* W_g   = (const float*)d_in[18];
    const float* b_g   = (const float*)d_in[19];
    const float* W_c   = (const float*)d_in[20];
    const float* b_c   = (const float*)d_in[21];

    float* out = (float*)d_out;
    float* out_logits = out;
    float* out_r      = out + BB * NCLS;

    bf16 *xh = bsym(g_x_hi), *xl = bsym(g_x_lo);
    bf16 *xsh = bsym(g_xs_hi), *xsl = bsym(g_xs_lo);
    bf16 *fh = bsym(g_f_hi), *fl = bsym(g_f_lo);
    bf16 *sfh = bsym(g_sf_hi), *sfl = bsym(g_sf_lo);
    bf16 *Wph = bsym(g_Wp_hi), *Wpl = bsym(g_Wp_lo);
    bf16 *Wsh = bsym(g_Ws_hi), *Wsl = bsym(g_Ws_lo);
    bf16 *Wlmh = bsym(g_Wlm_hi), *Wlml = bsym(g_Wlm_lo);
    bf16 *Wlsh = bsym(g_Wls_hi), *Wlsl = bsym(g_Wls_lo);
    bf16 *Whlh = bsym(g_Whl_hi), *Whll = bsym(g_Whl_lo);
    bf16 *Wish = bsym(g_Wis_hi), *Wisl = bsym(g_Wis_lo);
    bf16 *Whsh = bsym(g_Whs_hi), *Whsl = bsym(g_Whs_lo);
    bf16 *Wch = bsym(g_Wc_hi), *Wcl = bsym(g_Wc_lo);

    float* sfeats = fsym(g_sfeats);
    float* sgpre  = fsym(g_sgpre);
    float* lgpre  = fsym(g_lgpre);
    float* Gs = fsym(g_Gs);
    float* Gl = fsym(g_Gl);
    float* hl = fsym(g_hl);
    float* cl = fsym(g_cl);
    float* hs = fsym(g_hs);
    float* cs = fsym(g_cs);
    bf16* hlh = bsym(g_hl_hi); bf16* hll = bsym(g_hl_lo);
    bf16* hsh = bsym(g_hs_hi); bf16* hsl = bsym(g_hs_lo);

    const int TPB = 256;
    auto blks = [](long n) { return (int)((n + 255) / 256); };

    // ---- split inputs & weights into bf16 pairs
    split_kernel<<<blks((long)MBT * 2048), TPB>>>(x, xh, xl, MBT * 2048);
    split_kernel<<<blks((long)MBT * 1280), TPB>>>(xs, xsh, xsl, MBT * 1280);
    split_kernel<<<blks(2048L * 2048), TPB>>>(W_p, Wph, Wpl, 2048 * 2048);
    split_kernel<<<blks(512L * 1280), TPB>>>(W_s, Wsh, Wsl, 512 * 1280);
    splitw_kernel<<<blks(4096L * 2048), TPB>>>(Wih_l, 2560, 0,    Wlmh, Wlml, 4096, 2048);
    splitw_kernel<<<blks(4096L * 512),  TPB>>>(Wih_l, 2560, 2048, Wlsh, Wlsl, 4096, 512);
    split_kernel<<<blks(4096L * 1024), TPB>>>(Whh_l, Whlh, Whll, 4096 * 1024);
    split_kernel<<<blks(2048L * 512), TPB>>>(Wih_s, Wish, Wisl, 2048 * 512);
    split_kernel<<<blks(2048L * 512), TPB>>>(Whh_s, Whsh, Whsl, 2048 * 512);
    split_kernel<<<blks((long)NCLS * 1024), TPB>>>(W_c, Wch, Wcl, NCLS * 1024);
    zero_states_kernel<<<blks(BB * LL), TPB>>>(hl, cl, hs, cs, hlh, hll, hsh, hsl);

    // ---- Phase 1: time-parallel GEMMs
    // feats(split) = relu(BN(x @ W_p^T + b_p))
    gemm3_kernel<128,128><<<dim3(2048/128, MBT/128), 256>>>(
        xh, xl, 2048, Wph, Wpl, 2048, MBT, 2048, 2048,
        b_p, nullptr, nullptr, 0, g_p, be_p,
        nullptr, 0, 0, fh, fl, 2048);
    // sfeats(fp32 + split) = relu(BN(xs @ W_s^T + b_s))
    gemm3_kernel<128,128><<<dim3(512/128, MBT/128), 256>>>(
        xsh, xsl, 1280, Wsh, Wsl, 1280, MBT, 512, 1280,
        b_s, nullptr, nullptr, 0, g_s, be_s,
        sfeats, 512, 0, sfh, sfl, 512);
    // sgpre = sfeats @ Wih_s^T + bih_s + bhh_s
    gemm3_kernel<128,128><<<dim3(2048/128, MBT/128), 256>>>(
        sfh, sfl, 512, Wish, Wisl, 512, MBT, 2048, 512,
        bih_s, bhh_s, nullptr, 0, nullptr, nullptr,
        sgpre, 2048, 0, nullptr, nullptr, 0);
    // lgpre = feats @ Wih_l[:, :2048]^T + bih_l + bhh_l
    gemm3_kernel<128,128><<<dim3(4096/128, MBT/128), 256>>>(
        fh, fl, 2048, Wlmh, Wlml, 2048, MBT, 4096, 2048,
        bih_l, bhh_l, nullptr, 0, nullptr, nullptr,
        lgpre, 4096, 0, nullptr, nullptr, 0);
    // lgpre += sfeats @ Wih_l[:, 2048:2560]^T
    gemm3_kernel<128,128><<<dim3(4096/128, MBT/128), 256>>>(
        sfh, sfl, 512, Wlsh, Wlsl, 512, MBT, 4096, 512,
        nullptr, nullptr, nullptr, 0, nullptr, nullptr,
        lgpre, 4096, 1, nullptr, nullptr, 0);

    // ---- Phase 2: recurrence
    for (int t = 0; t < TT; t++) {
        int cur = t & 1, nxt = 1 - cur;
        float* hl_c = hl + (size_t)cur * BB * LL;
        float* cl_c = cl + (size_t)cur * BB * LL;
        float* hl_n = hl + (size_t)nxt * BB * LL;
        float* cl_n = cl + (size_t)nxt * BB * LL;
        float* hs_c = hs + (size_t)cur * BB * SS;  (void)hs_c;
        float* cs_c = cs + (size_t)cur * BB * SS;
        float* hs_n = hs + (size_t)nxt * BB * SS;
        float* cs_n = cs + (size_t)nxt * BB * SS;
        bf16* hlh_c = hlh + (size_t)cur * BB * LL;
        bf16* hll_c = hll + (size_t)cur * BB * LL;
        bf16* hlh_n = hlh + (size_t)nxt * BB * LL;
        bf16* hll_n = hll + (size_t)nxt * BB * LL;
        bf16* hsh_c = hsh + (size_t)cur * BB * SS;
        bf16* hsl_c = hsl + (size_t)cur * BB * SS;
        bf16* hsh_n = hsh + (size_t)nxt * BB * SS;
        bf16* hsl_n = hsl + (size_t)nxt * BB * SS;
        float* r_t = out_r + (size_t)t * BB * 2;

        // Gs = sgpre[:,t,:] + h_s @ Whh_s^T
        gemm3_kernel<64,64><<<dim3(2048/64, BB/64), 64>>>(
            hsh_c, hsl_c, 512, Whsh, Whsl, 512, BB, 2048, 512,
            nullptr, nullptr, sgpre + (size_t)t * 2048, TT * 2048, nullptr, nullptr,
            Gs, 2048, 0, nullptr, nullptr, 0);
        small_act_kernel<<<blks(BB * SS), TPB>>>(Gs, cs_c, hs_n, cs_n, hsh_n, hsl_n);

        gate_kernel<<<BB, 256>>>(sfeats, t, hl_c, cl_c, W_g, b_g, r_t);

        // Gl = lgpre[:,t,:] + h_l @ Whh_l^T
        gemm3_kernel<64,128><<<dim3(4096/128, BB/64), 128>>>(
            hlh_c, hll_c, 1024, Whlh, Whll, 1024, BB, 4096, 1024,
            nullptr, nullptr, lgpre + (size_t)t * 4096, TT * 4096, nullptr, nullptr,
            Gl, 4096, 0, nullptr, nullptr, 0);
        large_act_merge_kernel<<<blks(BB * LL), TPB>>>(
            Gl, hl_c, cl_c, hs_n, cs_n, r_t, hl_n, cl_n, hlh_n, hll_n);
    }

    // ---- classifier on final h_l (buffer 0 after 64 steps)
    gemm3_kernel<64,64><<<dim3((NCLS + 63) / 64, BB / 64), 64>>>(
        hlh, hll, 1024, Wch, Wcl, 1024, BB, NCLS, 1024,
        b_c, nullptr, nullptr, 0, nullptr, nullptr,
        out_logits, NCLS, 0, nullptr, nullptr, 0);
}

// round 4
// speedup vs baseline: 1.8983x; 1.3799x over previous
#include <cuda_runtime.h>
#include <cuda_bf16.h>
#include <math.h>
#include <stdint.h>

// ---------------------------------------------------------------------------
// Problem constants
// ---------------------------------------------------------------------------
#define BB 256
#define TT 64
#define LL 1024
#define SS 512
#define NCLS 239
#define MBT (BB * TT)          // 16384

typedef __nv_bfloat16 bf16;

// ---------------------------------------------------------------------------
// Scratch (device globals; no runtime allocation allowed)
// ---------------------------------------------------------------------------
__device__ bf16 g_x_hi  [MBT * 2048];
__device__ bf16 g_x_lo  [MBT * 2048];
__device__ bf16 g_xs_hi [MBT * 1280];
__device__ bf16 g_xs_lo [MBT * 1280];
__device__ bf16 g_f_hi  [MBT * 2048];
__device__ bf16 g_f_lo  [MBT * 2048];
__device__ bf16 g_sf_hi [MBT * 512];
__device__ bf16 g_sf_lo [MBT * 512];
__device__ bf16 g_Wp_hi [2048 * 2048];
__device__ bf16 g_Wp_lo [2048 * 2048];
__device__ bf16 g_Ws_hi [512 * 1280];
__device__ bf16 g_Ws_lo [512 * 1280];
__device__ bf16 g_Wl_hi [4096 * 2560];   // Wih_l full (K-concat GEMM)
__device__ bf16 g_Wl_lo [4096 * 2560];
__device__ bf16 g_Whl_hi[4096 * 1024];   // Whh_l
__device__ bf16 g_Whl_lo[4096 * 1024];
__device__ bf16 g_Wis_hi[2048 * 512];    // Wih_s
__device__ bf16 g_Wis_lo[2048 * 512];
__device__ bf16 g_Whs_hi[2048 * 512];    // Whh_s
__device__ bf16 g_Whs_lo[2048 * 512];
__device__ bf16 g_Wc_hi [NCLS * 1024];
__device__ bf16 g_Wc_lo [NCLS * 1024];
__device__ float g_sfeats[MBT * 512];
__device__ float g_sgpre [MBT * 2048];
__device__ float g_lgpre [MBT * 4096];
__device__ float g_Gs[BB * 2048];
__device__ float g_Gl[BB * 4096];
__device__ float g_hl[2][BB * LL];
__device__ float g_cl[2][BB * LL];
__device__ float g_hs[2][BB * SS];
__device__ float g_cs[2][BB * SS];
__device__ bf16 g_hl_hi[2][BB * LL];
__device__ bf16 g_hl_lo[2][BB * LL];
__device__ bf16 g_hs_hi[2][BB * SS];
__device__ bf16 g_hs_lo[2][BB * SS];

// ---------------------------------------------------------------------------
// PTX helpers (legacy tensor path only — harness targets compute_100)
// ---------------------------------------------------------------------------
__device__ __forceinline__ uint32_t smem_u32(const void* p) {
    return (uint32_t)__cvta_generic_to_shared(p);
}
__device__ __forceinline__ void cp16(uint32_t dst, const void* src, int srcsize) {
    asm volatile("cp.async.cg.shared.global [%0], [%1], 16, %2;\n"
                 :: "r"(dst), "l"(src), "r"(srcsize));
}
__device__ __forceinline__ void cp_commit() {
    asm volatile("cp.async.commit_group;\n");
}
template<int N>
__device__ __forceinline__ void cp_wait() {
    asm volatile("cp.async.wait_group %0;\n" :: "n"(N));
}
__device__ __forceinline__ void ldsm4(uint32_t* r, uint32_t addr) {
    asm volatile("ldmatrix.sync.aligned.m8n8.x4.shared.b16 {%0,%1,%2,%3}, [%4];\n"
                 : "=r"(r[0]), "=r"(r[1]), "=r"(r[2]), "=r"(r[3]) : "r"(addr));
}
__device__ __forceinline__ void mma_bf16(float* d, const uint32_t* a, uint32_t b0, uint32_t b1) {
    asm volatile("mma.sync.aligned.m16n8k16.row.col.f32.bf16.bf16.f32 "
                 "{%0,%1,%2,%3},{%4,%5,%6,%7},{%8,%9},{%0,%1,%2,%3};\n"
                 : "+f"(d[0]), "+f"(d[1]), "+f"(d[2]), "+f"(d[3])
                 : "r"(a[0]), "r"(a[1]), "r"(a[2]), "r"(a[3]), "r"(b0), "r"(b1));
}

// ---------------------------------------------------------------------------
// Split-bf16 triple-product GEMM core (4-stage cp.async pipeline).
//   C[M,N] = epi( A@W^T ), A = A_hi+A_lo, W = W_hi+W_lo, computed as
//   Ahi*Whi + Ahi*Wlo + Alo*Whi. A may be a K-concat: cols [0,K1) from A,
//   [K1,K) from A2 (K1 % 32 == 0). BM=BN=128, 256 threads, K % 32 == 0.
// ---------------------------------------------------------------------------
#define LDSH 40                       // halves per smem row (padded)
#define GSMEM (8 * 128 * LDSH * 2)    // 4 stages * (A + B) = 81920 bytes

__device__ __forceinline__ void gemm_core(
    char* smem, int bx, int by,
    const bf16* __restrict__ Ahi, const bf16* __restrict__ Alo, int lda,
    const bf16* __restrict__ A2hi, const bf16* __restrict__ A2lo, int lda2, int K1,
    const bf16* __restrict__ Bhi, const bf16* __restrict__ Blo, int ldb,
    int N, int K,
    const float* __restrict__ b1, const float* __restrict__ b2,
    const float* __restrict__ addsrc, int ldadd,
    const float* __restrict__ gamma, const float* __restrict__ beta,
    float* __restrict__ Cf, int ldc,
    bf16* __restrict__ Chi, bf16* __restrict__ Clo, int ldsp)
{
    constexpr int BM = 128, BN = 128, NT = 256;
    const int tid  = threadIdx.x;
    const int lane = tid & 31;
    const int wid  = tid >> 5;
    const int wm   = wid >> 2;          // 2 warp rows (64 each)
    const int wn   = wid & 3;           // 4 warp cols (32 each)
    const int bm   = by * BM;
    const int bn   = bx * BN;

    const int NK = K / 32;
    const int NS = 3 * NK;

    float acc[4][4][4];
#pragma unroll
    for (int i = 0; i < 4; i++)
#pragma unroll
        for (int j = 0; j < 4; j++)
#pragma unroll
            for (int r = 0; r < 4; r++) acc[i][j][r] = 0.f;

    auto stage = [&](int s) {
        int p  = s / NK;
        int k0 = (s - p * NK) * 32;
        const bf16* Ap; int ald, ak;
        if (k0 < K1) { Ap = (p == 2) ? Alo  : Ahi;  ald = lda;  ak = k0; }
        else         { Ap = (p == 2) ? A2lo : A2hi; ald = lda2; ak = k0 - K1; }
        const bf16* Bp = (p == 1) ? Blo : Bhi;
        uint32_t ab = smem_u32(smem) + (s & 3) * (BM * LDSH * 2);
        uint32_t bb = smem_u32(smem) + (4 + (s & 3)) * (BM * LDSH * 2);
#pragma unroll
        for (int v = tid; v < BM * 4; v += NT) {
            int row = v >> 2, kc = (v & 3) * 8;
            cp16(ab + (row * LDSH + kc) * 2,
                 Ap + (size_t)(bm + row) * ald + ak + kc, 16);
        }
#pragma unroll
        for (int v = tid; v < BN * 4; v += NT) {
            int row = v >> 2, kc = (v & 3) * 8;
            int n = bn + row;
            bool ok = (n < N);
            cp16(bb + (row * LDSH + kc) * 2,
                 Bp + (size_t)(ok ? n : 0) * ldb + k0 + kc, ok ? 16 : 0);
        }
    };

    stage(0); cp_commit();
    if (NS > 1) stage(1);
    cp_commit();
    if (NS > 2) stage(2);
    cp_commit();

    for (int s = 0; s < NS; s++) {
        cp_wait<2>();
        __syncthreads();
        if (s + 3 < NS) stage(s + 3);
        cp_commit();

        uint32_t asb = smem_u32(smem) + (s & 3) * (BM * LDSH * 2);
        uint32_t bsb = smem_u32(smem) + (4 + (s & 3)) * (BM * LDSH * 2);
#pragma unroll
        for (int ks = 0; ks < 32; ks += 16) {
            uint32_t a[4][4], b[4][2];
#pragma unroll
            for (int mi = 0; mi < 4; mi++) {
                int row = wm * 64 + mi * 16 + (lane & 15);
                int kk  = ks + (lane >> 4) * 8;
                ldsm4(a[mi], asb + (row * LDSH + kk) * 2);
            }
#pragma unroll
            for (int ng = 0; ng < 2; ng++) {
                int row = wn * 32 + ng * 16 + (lane & 7) + ((lane >> 4) << 3);
                int kk  = ks + (((lane >> 3) & 1) << 3);
                uint32_t t[4];
                ldsm4(t, bsb + (row * LDSH + kk) * 2);
                b[2 * ng][0] = t[0]; b[2 * ng][1] = t[1];
                b[2 * ng + 1][0] = t[2]; b[2 * ng + 1][1] = t[3];
            }
#pragma unroll
            for (int mi = 0; mi < 4; mi++)
#pragma unroll
                for (int nj = 0; nj < 4; nj++)
                    mma_bf16(acc[mi][nj], a[mi], b[nj][0], b[nj][1]);
        }
        __syncthreads();
    }

    // ---- epilogue (register-resident)
    const float inv_std = rsqrtf(1.0f + 1e-5f);
    const int g  = lane >> 2;
    const int tg = lane & 3;
#pragma unroll
    for (int mi = 0; mi < 4; mi++)
#pragma unroll
        for (int nj = 0; nj < 4; nj++)
#pragma unroll
            for (int r = 0; r < 4; r++) {
                int m = bm + wm * 64 + mi * 16 + g + ((r >> 1) << 3);
                int n = bn + wn * 32 + nj * 8 + tg * 2 + (r & 1);
                if (n >= N) continue;
                float v = acc[mi][nj][r];
                if (b1)     v += b1[n];
                if (b2)     v += b2[n];
                if (addsrc) v += addsrc[(size_t)m * ldadd + n];
                if (gamma)  v = fmaxf(0.f, v * (gamma[n] * inv_std) + beta[n]);
                if (Cf)     Cf[(size_t)m * ldc + n] = v;
                if (Chi) {
                    bf16 h = __float2bfloat16(v);
                    Chi[(size_t)m * ldsp + n] = h;
                    Clo[(size_t)m * ldsp + n] = __float2bfloat16(v - __bfloat162float(h));
                }
            }
}

// standalone GEMM launcher
__global__ void __launch_bounds__(256)
gemm3_kernel(const bf16* Ahi, const bf16* Alo, int lda,
             const bf16* A2hi, const bf16* A2lo, int lda2, int K1,
             const bf16* Bhi, const bf16* Blo, int ldb,
             int N, int K,
             const float* b1, const float* b2,
             const float* addsrc, int ldadd,
             const float* gamma, const float* beta,
             float* Cf, int ldc,
             bf16* Chi, bf16* Clo, int ldsp)
{
    extern __shared__ char smem[];
    gemm_core(smem, blockIdx.x, blockIdx.y,
              Ahi, Alo, lda, A2hi, A2lo, lda2, K1, Bhi, Blo, ldb, N, K,
              b1, b2, addsrc, ldadd, gamma, beta, Cf, ldc, Chi, Clo, ldsp);
}

// fused per-step GEMM: z==0 -> Gs (N=2048,K=512), z==1 -> Gl (N=4096,K=1024)
__global__ void __launch_bounds__(256)
step_gemm_kernel(const bf16* hsh, const bf16* hsl, const bf16* Whsh, const bf16* Whsl,
                 const float* sgpre_t,
                 const bf16* hlh, const bf16* hll, const bf16* Whlh, const bf16* Whll,
                 const float* lgpre_t,
                 float* Gs, float* Gl)
{
    extern __shared__ char smem[];
    if (blockIdx.z == 0) {
        if (blockIdx.x >= 2048 / 128) return;
        gemm_core(smem, blockIdx.x, blockIdx.y,
                  hsh, hsl, 512, nullptr, nullptr, 0, 512,
                  Whsh, Whsl, 512, 2048, 512,
                  nullptr, nullptr, sgpre_t, TT * 2048, nullptr, nullptr,
                  Gs, 2048, nullptr, nullptr, 0);
    } else {
        gemm_core(smem, blockIdx.x, blockIdx.y,
                  hlh, hll, 1024, nullptr, nullptr, 0, 1024,
                  Whlh, Whll, 1024, 4096, 1024,
                  nullptr, nullptr, lgpre_t, TT * 4096, nullptr, nullptr,
                  Gl, 4096, nullptr, nullptr, 0);
    }
}

// ---------------------------------------------------------------------------
// Elementwise kernels
// ---------------------------------------------------------------------------
__device__ __forceinline__ float sigf(float x) { return 1.f / (1.f + expf(-x)); }
__device__ __forceinline__ void split1(float v, bf16* hi, bf16* lo, size_t i) {
    bf16 h = __float2bfloat16(v);
    hi[i] = h;
    lo[i] = __float2bfloat16(v - __bfloat162float(h));
}

// vectorized fp32 -> bf16 hi/lo split (n % 4 == 0)
__global__ void split4_kernel(const float4* __restrict__ src,
                              __nv_bfloat162* __restrict__ hi,
                              __nv_bfloat162* __restrict__ lo, int n4)
{
    int i = blockIdx.x * blockDim.x + threadIdx.x;
    if (i >= n4) return;
    float4 v = src[i];
    bf16 h0 = __float2bfloat16(v.x), h1 = __float2bfloat16(v.y);
    bf16 h2 = __float2bfloat16(v.z), h3 = __float2bfloat16(v.w);
    bf16 l0 = __float2bfloat16(v.x - __bfloat162float(h0));
    bf16 l1 = __float2bfloat16(v.y - __bfloat162float(h1));
    bf16 l2 = __float2bfloat16(v.z - __bfloat162float(h2));
    bf16 l3 = __float2bfloat16(v.w - __bfloat162float(h3));
    hi[2 * i]     = __nv_bfloat162(h0, h1);
    hi[2 * i + 1] = __nv_bfloat162(h2, h3);
    lo[2 * i]     = __nv_bfloat162(l0, l1);
    lo[2 * i + 1] = __nv_bfloat162(l2, l3);
}

__global__ void zero_states_kernel(float* hl, float* cl, float* hs, float* cs,
                                   bf16* hlh, bf16* hll, bf16* hsh, bf16* hsl)
{
    int i = blockIdx.x * blockDim.x + threadIdx.x;
    if (i < BB * LL) { hl[i] = 0.f; cl[i] = 0.f; hlh[i] = __float2bfloat16(0.f); hll[i] = __float2bfloat16(0.f); }
    if (i < BB * SS) { hs[i] = 0.f; cs[i] = 0.f; hsh[i] = __float2bfloat16(0.f); hsl[i] = __float2bfloat16(0.f); }
}

__global__ void small_act_kernel(const float* __restrict__ G,
                                 const float* __restrict__ c_old,
                                 float* __restrict__ h_new, float* __restrict__ c_new,
                                 bf16* __restrict__ hh, bf16* __restrict__ hl)
{
    int idx = blockIdx.x * blockDim.x + threadIdx.x;
    if (idx >= BB * SS) return;
    int b = idx >> 9, n = idx & (SS - 1);
    const float* g = G + (size_t)b * (4 * SS);
    float i_ = sigf(g[n]);
    float f_ = sigf(g[SS + n]);
    float gg = tanhf(g[2 * SS + n]);
    float o_ = sigf(g[3 * SS + n]);
    float c2 = f_ * c_old[idx] + i_ * gg;
    float h2 = o_ * tanhf(c2);
    c_new[idx] = c2;
    h_new[idx] = h2;
    split1(h2, hh, hl, idx);
}

// fused gate + large LSTM act + straight-through merge. One block per batch row.
__global__ void __launch_bounds__(256)
gate_merge_kernel(const float* __restrict__ G,
                  const float* __restrict__ sfeats, int t,
                  const float* __restrict__ h_old, const float* __restrict__ c_old,
                  const float* __restrict__ h_s_new, const float* __restrict__ c_s_new,
                  const float* __restrict__ W_g, const float* __restrict__ b_g,
                  float* __restrict__ r_out,
                  float* __restrict__ h_new, float* __restrict__ c_new,
                  bf16* __restrict__ hh, bf16* __restrict__ hl)
{
    const int b   = blockIdx.x;
    const int tid = threadIdx.x;
    const float* s = sfeats + ((size_t)b * TT + t) * SS;
    const float* h = h_old + (size_t)b * LL;
    const float* c = c_old + (size_t)b * LL;
    const float* w0 = W_g;
    const float* w1 = W_g + 2560;

    // gate: r = one_hot(argmax([s_t,h_l,c_l] @ W_g^T + b_g))
    float p0 = 0.f, p1 = 0.f;
    for (int j = tid; j < SS; j += 256) { float v = s[j]; p0 += v * w0[j]; p1 += v * w1[j]; }
    for (int j = tid; j < LL; j += 256) { float v = h[j]; p0 += v * w0[SS + j]; p1 += v * w1[SS + j]; }
    for (int j = tid; j < LL; j += 256) { float v = c[j]; p0 += v * w0[SS + LL + j]; p1 += v * w1[SS + LL + j]; }
    __shared__ float s0[256], s1[256];
    __shared__ float r0sh;
    s0[tid] = p0; s1[tid] = p1;
    __syncthreads();
    for (int st = 128; st > 0; st >>= 1) {
        if (tid < st) { s0[tid] += s0[tid + st]; s1[tid] += s1[tid + st]; }
        __syncthreads();
    }
    if (tid == 0) {
        float r0 = (s0[0] + b_g[0] >= s1[0] + b_g[1]) ? 1.f : 0.f;
        r0sh = r0;
        r_out[b * 2 + 0] = r0;
        r_out[b * 2 + 1] = 1.f - r0;
    }
    __syncthreads();
    const float r0 = r0sh, r1 = 1.f - r0sh;

    const float* g = G + (size_t)b * (4 * LL);
#pragma unroll
    for (int n = tid; n < LL; n += 256) {
        size_t idx = (size_t)b * LL + n;
        float i_ = sigf(g[n]);
        float f_ = sigf(g[LL + n]);
        float gg = tanhf(g[2 * LL + n]);
        float o_ = sigf(g[3 * LL + n]);
        float c_ln = f_ * c_old[idx] + i_ * gg;
        float h_ln = o_ * tanhf(c_ln);
        float ph = (n < SS) ? h_s_new[b * SS + n] : h_old[idx];
        float pc = (n < SS) ? c_s_new[b * SS + n] : c_old[idx];
        float h2 = r0 * h_ln + r1 * ph;
        c_new[idx] = r0 * c_ln + r1 * pc;
        h_new[idx] = h2;
        split1(h2, hh, hl, idx);
    }
}

// ---------------------------------------------------------------------------
// Launch
// ---------------------------------------------------------------------------
static inline float* fsym(const void* s) { void* p = nullptr; cudaGetSymbolAddress(&p, s); return (float*)p; }
static inline bf16*  bsym(const void* s) { void* p = nullptr; cudaGetSymbolAddress(&p, s); return (bf16*)p; }

extern "C" void kernel_launch(void* const* d_in, const int* in_sizes, int n_in,
                              void* d_out, int out_size)
{
    const float* x     = (const float*)d_in[0];
    const float* xs    = (const float*)d_in[1];
    const float* W_p   = (const float*)d_in[2];
    const float* b_p   = (const float*)d_in[3];
    const float* g_p   = (const float*)d_in[4];
    const float* be_p  = (const float*)d_in[5];
    const float* W_s   = (const float*)d_in[6];
    const float* b_s   = (const float*)d_in[7];
    const float* g_s   = (const float*)d_in[8];
    const float* be_s  = (const float*)d_in[9];
    const float* Wih_l = (const float*)d_in[10];
    const float* Whh_l = (const float*)d_in[11];
    const float* bih_l = (const float*)d_in[12];
    const float* bhh_l = (const float*)d_in[13];
    const float* Wih_s = (const float*)d_in[14];
    const float* Whh_s = (const float*)d_in[15];
    const float* bih_s = (const float*)d_in[16];
    const float* bhh_s = (const float*)d_in[17];
    const float* W_g   = (const float*)d_in[18];
    const float* b_g   = (const float*)d_in[19];
    const float* W_c   = (const float*)d_in[20];
    const float* b_c   = (const float*)d_in[21];

    float* out = (float*)d_out;
    float* out_logits = out;
    float* out_r      = out + BB * NCLS;

    bf16 *xh = bsym(g_x_hi), *xl = bsym(g_x_lo);
    bf16 *xsh = bsym(g_xs_hi), *xsl = bsym(g_xs_lo);
    bf16 *fh = bsym(g_f_hi), *fl = bsym(g_f_lo);
    bf16 *sfh = bsym(g_sf_hi), *sfl = bsym(g_sf_lo);
    bf16 *Wph = bsym(g_Wp_hi), *Wpl = bsym(g_Wp_lo);
    bf16 *Wsh = bsym(g_Ws_hi), *Wsl = bsym(g_Ws_lo);
    bf16 *Wlh = bsym(g_Wl_hi), *Wll = bsym(g_Wl_lo);
    bf16 *Whlh = bsym(g_Whl_hi), *Whll = bsym(g_Whl_lo);
    bf16 *Wish = bsym(g_Wis_hi), *Wisl = bsym(g_Wis_lo);
    bf16 *Whsh = bsym(g_Whs_hi), *Whsl = bsym(g_Whs_lo);
    bf16 *Wch = bsym(g_Wc_hi), *Wcl = bsym(g_Wc_lo);

    float* sfeats = fsym(g_sfeats);
    float* sgpre  = fsym(g_sgpre);
    float* lgpre  = fsym(g_lgpre);
    float* Gs = fsym(g_Gs);
    float* Gl = fsym(g_Gl);
    float* hl = fsym(g_hl);
    float* cl = fsym(g_cl);
    float* hs = fsym(g_hs);
    float* cs = fsym(g_cs);
    bf16* hlh = bsym(g_hl_hi); bf16* hll = bsym(g_hl_lo);
    bf16* hsh = bsym(g_hs_hi); bf16* hsl = bsym(g_hs_lo);

    cudaFuncSetAttribute(gemm3_kernel, cudaFuncAttributeMaxDynamicSharedMemorySize, GSMEM);
    cudaFuncSetAttribute(step_gemm_kernel, cudaFuncAttributeMaxDynamicSharedMemorySize, GSMEM);

    const int TPB = 256;
    auto blks4 = [](long n) { return (int)((n / 4 + 255) / 256); };

    // ---- split inputs & weights into bf16 pairs (vectorized)
    auto SPL = [&](const float* s, bf16* h, bf16* l, long n) {
        split4_kernel<<<blks4(n), TPB>>>((const float4*)s, (__nv_bfloat162*)h,
                                         (__nv_bfloat162*)l, (int)(n / 4));
    };
    SPL(x, xh, xl, (long)MBT * 2048);
    SPL(xs, xsh, xsl, (long)MBT * 1280);
    SPL(W_p, Wph, Wpl, 2048L * 2048);
    SPL(W_s, Wsh, Wsl, 512L * 1280);
    SPL(Wih_l, Wlh, Wll, 4096L * 2560);
    SPL(Whh_l, Whlh, Whll, 4096L * 1024);
    SPL(Wih_s, Wish, Wisl, 2048L * 512);
    SPL(Whh_s, Whsh, Whsl, 2048L * 512);
    SPL(W_c, Wch, Wcl, (long)NCLS * 1024);   // NCLS*1024 % 4 == 0
    zero_states_kernel<<<(BB * LL + 255) / 256, TPB>>>(hl, cl, hs, cs, hlh, hll, hsh, hsl);

    // ---- Phase 1: time-parallel GEMMs
    // feats(split) = relu(BN(x @ W_p^T + b_p))
    gemm3_kernel<<<dim3(2048 / 128, MBT / 128), 256, GSMEM>>>(
        xh, xl, 2048, nullptr, nullptr, 0, 2048,
        Wph, Wpl, 2048, 2048, 2048,
        b_p, nullptr, nullptr, 0, g_p, be_p,
        nullptr, 0, fh, fl, 2048);
    // sfeats(fp32+split) = relu(BN(xs @ W_s^T + b_s))
    gemm3_kernel<<<dim3(512 / 128, MBT / 128), 256, GSMEM>>>(
        xsh, xsl, 1280, nullptr, nullptr, 0, 1280,
        Wsh, Wsl, 1280, 512, 1280,
        b_s, nullptr, nullptr, 0, g_s, be_s,
        sfeats, 512, sfh, sfl, 512);
    // sgpre = sfeats @ Wih_s^T + bih_s + bhh_s
    gemm3_kernel<<<dim3(2048 / 128, MBT / 128), 256, GSMEM>>>(
        sfh, sfl, 512, nullptr, nullptr, 0, 512,
        Wish, Wisl, 512, 2048, 512,
        bih_s, bhh_s, nullptr, 0, nullptr, nullptr,
        sgpre, 2048, nullptr, nullptr, 0);
    // lgpre = [feats, sfeats] @ Wih_l^T + bih_l + bhh_l   (K-concat 2048+512)
    gemm3_kernel<<<dim3(4096 / 128, MBT / 128), 256, GSMEM>>>(
        fh, fl, 2048, sfh, sfl, 512, 2048,
        Wlh, Wll, 2560, 4096, 2560,
        bih_l, bhh_l, nullptr, 0, nullptr, nullptr,
        lgpre, 4096, nullptr, nullptr, 0);

    // ---- Phase 2: recurrence (3 launches per step)
    for (int t = 0; t < TT; t++) {
        int cur = t & 1, nxt = 1 - cur;
        float* hl_c = hl + (size_t)cur * BB * LL;
        float* cl_c = cl + (size_t)cur * BB * LL;
        float* hl_n = hl + (size_t)nxt * BB * LL;
        float* cl_n = cl + (size_t)nxt * BB * LL;
        float* cs_c = cs + (size_t)cur * BB * SS;
        float* hs_n = hs + (size_t)nxt * BB * SS;
        float* cs_n = cs + (size_t)nxt * BB * SS;
        bf16* hlh_c = hlh + (size_t)cur * BB * LL;
        bf16* hll_c = hll + (size_t)cur * BB * LL;
        bf16* hlh_n = hlh + (size_t)nxt * BB * LL;
        bf16* hll_n = hll + (size_t)nxt * BB * LL;
        bf16* hsh_c = hsh + (size_t)cur * BB * SS;
        bf16* hsl_c = hsl + (size_t)cur * BB * SS;
        bf16* hsh_n = hsh + (size_t)nxt * BB * SS;
        bf16* hsl_n = hsl + (size_t)nxt * BB * SS;
        float* r_t = out_r + (size_t)t * BB * 2;

        // Gs and Gl in one launch
        step_gemm_kernel<<<dim3(4096 / 128, BB / 128, 2), 256, GSMEM>>>(
            hsh_c, hsl_c, Whsh, Whsl, sgpre + (size_t)t * 2048,
            hlh_c, hll_c, Whlh, Whll, lgpre + (size_t)t * 4096,
            Gs, Gl);
        small_act_kernel<<<(BB * SS + 255) / 256, TPB>>>(Gs, cs_c, hs_n, cs_n, hsh_n, hsl_n);
        gate_merge_kernel<<<BB, 256>>>(Gl, sfeats, t, hl_c, cl_c, hs_n, cs_n,
                                       W_g, b_g, r_t, hl_n, cl_n, hlh_n, hll_n);
    }

    // ---- classifier on final h_l (buffer 0 after 64 steps)
    gemm3_kernel<<<dim3((NCLS + 127) / 128, BB / 128), 256, GSMEM>>>(
        hlh, hll, 1024, nullptr, nullptr, 0, 1024,
        Wch, Wcl, 1024, NCLS, 1024,
        b_c, nullptr, nullptr, 0, nullptr, nullptr,
        out_logits, NCLS, nullptr, nullptr, 0);
}

// round 5
// speedup vs baseline: 2.0134x; 1.0606x over previous
#include <cuda_runtime.h>
#include <cuda_bf16.h>
#include <math.h>
#include <stdint.h>

// ---------------------------------------------------------------------------
// Problem constants
// ---------------------------------------------------------------------------
#define BB 256
#define TT 64
#define LL 1024
#define SS 512
#define NCLS 239
#define MBT (BB * TT)          // 16384

typedef __nv_bfloat16 bf16;

// ---------------------------------------------------------------------------
// Scratch (device globals; no runtime allocation allowed)
// ---------------------------------------------------------------------------
__device__ bf16 g_x_hi  [MBT * 2048];
__device__ bf16 g_x_lo  [MBT * 2048];
__device__ bf16 g_xs_hi [MBT * 1280];
__device__ bf16 g_xs_lo [MBT * 1280];
__device__ bf16 g_f_hi  [MBT * 2048];
__device__ bf16 g_f_lo  [MBT * 2048];
__device__ bf16 g_sf_hi [MBT * 512];
__device__ bf16 g_sf_lo [MBT * 512];
__device__ bf16 g_Wp_hi [2048 * 2048];
__device__ bf16 g_Wp_lo [2048 * 2048];
__device__ bf16 g_Ws_hi [512 * 1280];
__device__ bf16 g_Ws_lo [512 * 1280];
__device__ bf16 g_Wl_hi [4096 * 2560];   // Wih_l full (K-concat GEMM)
__device__ bf16 g_Wl_lo [4096 * 2560];
__device__ bf16 g_Whl_hi[4096 * 1024];   // Whh_l
__device__ bf16 g_Whl_lo[4096 * 1024];
__device__ bf16 g_Wis_hi[2048 * 512];    // Wih_s
__device__ bf16 g_Wis_lo[2048 * 512];
__device__ bf16 g_Whs_hi[2048 * 512];    // Whh_s
__device__ bf16 g_Whs_lo[2048 * 512];
__device__ bf16 g_Wc_hi [NCLS * 1024];
__device__ bf16 g_Wc_lo [NCLS * 1024];
__device__ float g_sfeats[MBT * 512];
__device__ float g_sgpre [MBT * 2048];
__device__ float g_lgpre [MBT * 4096];
__device__ float g_Gs[BB * 2048];
__device__ float g_Gl[BB * 4096];
__device__ float g_hl[2][BB * LL];
__device__ float g_cl[2][BB * LL];
__device__ float g_hs[2][BB * SS];
__device__ float g_cs[2][BB * SS];
__device__ bf16 g_hl_hi[2][BB * LL];
__device__ bf16 g_hl_lo[2][BB * LL];
__device__ bf16 g_hs_hi[2][BB * SS];
__device__ bf16 g_hs_lo[2][BB * SS];

// ---------------------------------------------------------------------------
// PTX helpers (legacy tensor path only — harness targets compute_100)
// ---------------------------------------------------------------------------
__device__ __forceinline__ uint32_t smem_u32(const void* p) {
    return (uint32_t)__cvta_generic_to_shared(p);
}
__device__ __forceinline__ void cp16(uint32_t dst, const void* src, int srcsize) {
    asm volatile("cp.async.cg.shared.global [%0], [%1], 16, %2;\n"
                 :: "r"(dst), "l"(src), "r"(srcsize));
}
__device__ __forceinline__ void cp_commit() {
    asm volatile("cp.async.commit_group;\n");
}
template<int N>
__device__ __forceinline__ void cp_wait() {
    asm volatile("cp.async.wait_group %0;\n" :: "n"(N));
}
__device__ __forceinline__ void ldsm4(uint32_t* r, uint32_t addr) {
    asm volatile("ldmatrix.sync.aligned.m8n8.x4.shared.b16 {%0,%1,%2,%3}, [%4];\n"
                 : "=r"(r[0]), "=r"(r[1]), "=r"(r[2]), "=r"(r[3]) : "r"(addr));
}
__device__ __forceinline__ void mma_bf16(float* d, const uint32_t* a, uint32_t b0, uint32_t b1) {
    asm volatile("mma.sync.aligned.m16n8k16.row.col.f32.bf16.bf16.f32 "
                 "{%0,%1,%2,%3},{%4,%5,%6,%7},{%8,%9},{%0,%1,%2,%3};\n"
                 : "+f"(d[0]), "+f"(d[1]), "+f"(d[2]), "+f"(d[3])
                 : "r"(a[0]), "r"(a[1]), "r"(a[2]), "r"(a[3]), "r"(b0), "r"(b1));
}

// ---------------------------------------------------------------------------
// Split-bf16 triple-product GEMM core (4-stage cp.async pipeline, 1 sync/stage).
//   C[M,N] = epi( A@W^T ), A = A_hi+A_lo, W = W_hi+W_lo, computed as
//   Ahi*Whi + Ahi*Wlo + Alo*Whi. A may be a K-concat: cols [0,K1) from A,
//   [K1,K) from A2 (K1 % 32 == 0). BM=BN=128, 256 threads, K % 32 == 0.
// ---------------------------------------------------------------------------
#define LDSH 40                       // halves per smem row (padded)
#define GSMEM (8 * 128 * LDSH * 2)    // 4 stages * (A + B) = 81920 bytes

__device__ __forceinline__ void gemm_core(
    char* smem, int bx, int by,
    const bf16* __restrict__ Ahi, const bf16* __restrict__ Alo, int lda,
    const bf16* __restrict__ A2hi, const bf16* __restrict__ A2lo, int lda2, int K1,
    const bf16* __restrict__ Bhi, const bf16* __restrict__ Blo, int ldb,
    int N, int K,
    const float* __restrict__ b1, const float* __restrict__ b2,
    const float* __restrict__ addsrc, int ldadd,
    const float* __restrict__ gamma, const float* __restrict__ beta,
    float* __restrict__ Cf, int ldc,
    bf16* __restrict__ Chi, bf16* __restrict__ Clo, int ldsp)
{
    constexpr int BM = 128, BN = 128, NT = 256;
    const int tid  = threadIdx.x;
    const int lane = tid & 31;
    const int wid  = tid >> 5;
    const int wm   = wid >> 2;          // 2 warp rows (64 each)
    const int wn   = wid & 3;           // 4 warp cols (32 each)
    const int bm   = by * BM;
    const int bn   = bx * BN;

    const int NK = K / 32;
    const int NS = 3 * NK;

    float acc[4][4][4];
#pragma unroll
    for (int i = 0; i < 4; i++)
#pragma unroll
        for (int j = 0; j < 4; j++)
#pragma unroll
            for (int r = 0; r < 4; r++) acc[i][j][r] = 0.f;

    auto stage = [&](int s) {
        int p  = s / NK;
        int k0 = (s - p * NK) * 32;
        const bf16* Ap; int ald, ak;
        if (k0 < K1) { Ap = (p == 2) ? Alo  : Ahi;  ald = lda;  ak = k0; }
        else         { Ap = (p == 2) ? A2lo : A2hi; ald = lda2; ak = k0 - K1; }
        const bf16* Bp = (p == 1) ? Blo : Bhi;
        uint32_t ab = smem_u32(smem) + (s & 3) * (BM * LDSH * 2);
        uint32_t bb = smem_u32(smem) + (4 + (s & 3)) * (BM * LDSH * 2);
#pragma unroll
        for (int v = tid; v < BM * 4; v += NT) {
            int row = v >> 2, kc = (v & 3) * 8;
            cp16(ab + (row * LDSH + kc) * 2,
                 Ap + (size_t)(bm + row) * ald + ak + kc, 16);
        }
#pragma unroll
        for (int v = tid; v < BN * 4; v += NT) {
            int row = v >> 2, kc = (v & 3) * 8;
            int n = bn + row;
            bool ok = (n < N);
            cp16(bb + (row * LDSH + kc) * 2,
                 Bp + (size_t)(ok ? n : 0) * ldb + k0 + kc, ok ? 16 : 0);
        }
    };

    stage(0); cp_commit();
    if (NS > 1) stage(1);
    cp_commit();
    if (NS > 2) stage(2);
    cp_commit();

    for (int s = 0; s < NS; s++) {
        cp_wait<2>();
        __syncthreads();   // all warps done with stage s-1 reads; stage s data landed
        if (s + 3 < NS) stage(s + 3);
        cp_commit();

        uint32_t asb = smem_u32(smem) + (s & 3) * (BM * LDSH * 2);
        uint32_t bsb = smem_u32(smem) + (4 + (s & 3)) * (BM * LDSH * 2);
#pragma unroll
        for (int ks = 0; ks < 32; ks += 16) {
            uint32_t a[4][4], b[4][2];
#pragma unroll
            for (int mi = 0; mi < 4; mi++) {
                int row = wm * 64 + mi * 16 + (lane & 15);
                int kk  = ks + (lane >> 4) * 8;
                ldsm4(a[mi], asb + (row * LDSH + kk) * 2);
            }
#pragma unroll
            for (int ng = 0; ng < 2; ng++) {
                int row = wn * 32 + ng * 16 + (lane & 7) + ((lane >> 4) << 3);
                int kk  = ks + (((lane >> 3) & 1) << 3);
                uint32_t t[4];
                ldsm4(t, bsb + (row * LDSH + kk) * 2);
                b[2 * ng][0] = t[0]; b[2 * ng][1] = t[1];
                b[2 * ng + 1][0] = t[2]; b[2 * ng + 1][1] = t[3];
            }
#pragma unroll
            for (int mi = 0; mi < 4; mi++)
#pragma unroll
                for (int nj = 0; nj < 4; nj++)
                    mma_bf16(acc[mi][nj], a[mi], b[nj][0], b[nj][1]);
        }
    }

    // ---- epilogue (register-resident)
    const float inv_std = rsqrtf(1.0f + 1e-5f);
    const int g  = lane >> 2;
    const int tg = lane & 3;
#pragma unroll
    for (int mi = 0; mi < 4; mi++)
#pragma unroll
        for (int nj = 0; nj < 4; nj++)
#pragma unroll
            for (int r = 0; r < 4; r++) {
                int m = bm + wm * 64 + mi * 16 + g + ((r >> 1) << 3);
                int n = bn + wn * 32 + nj * 8 + tg * 2 + (r & 1);
                if (n >= N) continue;
                float v = acc[mi][nj][r];
                if (b1)     v += b1[n];
                if (b2)     v += b2[n];
                if (addsrc) v += addsrc[(size_t)m * ldadd + n];
                if (gamma)  v = fmaxf(0.f, v * (gamma[n] * inv_std) + beta[n]);
                if (Cf)     Cf[(size_t)m * ldc + n] = v;
                if (Chi) {
                    bf16 h = __float2bfloat16(v);
                    Chi[(size_t)m * ldsp + n] = h;
                    Clo[(size_t)m * ldsp + n] = __float2bfloat16(v - __bfloat162float(h));
                }
            }
}

// standalone GEMM launcher (2 CTAs/SM target)
__global__ void __launch_bounds__(256, 2)
gemm3_kernel(const bf16* Ahi, const bf16* Alo, int lda,
             const bf16* A2hi, const bf16* A2lo, int lda2, int K1,
             const bf16* Bhi, const bf16* Blo, int ldb,
             int N, int K,
             const float* b1, const float* b2,
             const float* addsrc, int ldadd,
             const float* gamma, const float* beta,
             float* Cf, int ldc,
             bf16* Chi, bf16* Clo, int ldsp)
{
    extern __shared__ char smem[];
    gemm_core(smem, blockIdx.x, blockIdx.y,
              Ahi, Alo, lda, A2hi, A2lo, lda2, K1, Bhi, Blo, ldb, N, K,
              b1, b2, addsrc, ldadd, gamma, beta, Cf, ldc, Chi, Clo, ldsp);
}

// fused per-step GEMM: z==0 -> Gs (N=2048,K=512), z==1 -> Gl (N=4096,K=1024)
__global__ void __launch_bounds__(256, 2)
step_gemm_kernel(const bf16* hsh, const bf16* hsl, const bf16* Whsh, const bf16* Whsl,
                 const float* sgpre_t,
                 const bf16* hlh, const bf16* hll, const bf16* Whlh, const bf16* Whll,
                 const float* lgpre_t,
                 float* Gs, float* Gl)
{
    extern __shared__ char smem[];
    if (blockIdx.z == 0) {
        if (blockIdx.x >= 2048 / 128) return;
        gemm_core(smem, blockIdx.x, blockIdx.y,
                  hsh, hsl, 512, nullptr, nullptr, 0, 512,
                  Whsh, Whsl, 512, 2048, 512,
                  nullptr, nullptr, sgpre_t, TT * 2048, nullptr, nullptr,
                  Gs, 2048, nullptr, nullptr, 0);
    } else {
        gemm_core(smem, blockIdx.x, blockIdx.y,
                  hlh, hll, 1024, nullptr, nullptr, 0, 1024,
                  Whlh, Whll, 1024, 4096, 1024,
                  nullptr, nullptr, lgpre_t, TT * 4096, nullptr, nullptr,
                  Gl, 4096, nullptr, nullptr, 0);
    }
}

// ---------------------------------------------------------------------------
// Elementwise kernels
// ---------------------------------------------------------------------------
__device__ __forceinline__ float sigf(float x) { return 1.f / (1.f + expf(-x)); }
__device__ __forceinline__ void split1(float v, bf16* hi, bf16* lo, size_t i) {
    bf16 h = __float2bfloat16(v);
    hi[i] = h;
    lo[i] = __float2bfloat16(v - __bfloat162float(h));
}

// one fused split kernel over all 9 tensors (float4-vectorized)
struct SJob { const float4* src; __nv_bfloat162* hi; __nv_bfloat162* lo; };
struct SJobs { SJob j[9]; unsigned cum[10]; };

__global__ void __launch_bounds__(256)
split_all_kernel(SJobs jb, unsigned total4)
{
    unsigned i = blockIdx.x * blockDim.x + threadIdx.x;
    if (i >= total4) return;
    int k = 0;
#pragma unroll
    for (int q = 0; q < 8; q++) if (i >= jb.cum[q + 1]) k = q + 1;
    unsigned off = i - jb.cum[k];
    float4 v = jb.j[k].src[off];
    bf16 h0 = __float2bfloat16(v.x), h1 = __float2bfloat16(v.y);
    bf16 h2 = __float2bfloat16(v.z), h3 = __float2bfloat16(v.w);
    bf16 l0 = __float2bfloat16(v.x - __bfloat162float(h0));
    bf16 l1 = __float2bfloat16(v.y - __bfloat162float(h1));
    bf16 l2 = __float2bfloat16(v.z - __bfloat162float(h2));
    bf16 l3 = __float2bfloat16(v.w - __bfloat162float(h3));
    jb.j[k].hi[2 * off]     = __nv_bfloat162(h0, h1);
    jb.j[k].hi[2 * off + 1] = __nv_bfloat162(h2, h3);
    jb.j[k].lo[2 * off]     = __nv_bfloat162(l0, l1);
    jb.j[k].lo[2 * off + 1] = __nv_bfloat162(l2, l3);
}

__global__ void zero_states_kernel(float* hl, float* cl, float* hs, float* cs,
                                   bf16* hlh, bf16* hll, bf16* hsh, bf16* hsl)
{
    int i = blockIdx.x * blockDim.x + threadIdx.x;
    if (i < BB * LL) { hl[i] = 0.f; cl[i] = 0.f; hlh[i] = __float2bfloat16(0.f); hll[i] = __float2bfloat16(0.f); }
    if (i < BB * SS) { hs[i] = 0.f; cs[i] = 0.f; hsh[i] = __float2bfloat16(0.f); hsl[i] = __float2bfloat16(0.f); }
}

// fused per-step post-GEMM kernel: small LSTM act + hard gate + large act/merge.
// One block per batch row.
__global__ void __launch_bounds__(256)
step_post_kernel(const float* __restrict__ Gs, const float* __restrict__ Gl,
                 const float* __restrict__ sfeats, int t,
                 const float* __restrict__ h_old, const float* __restrict__ c_old,
                 const float* __restrict__ cs_old,
                 float* __restrict__ hs_new, float* __restrict__ cs_new,
                 bf16* __restrict__ hsh, bf16* __restrict__ hsl,
                 const float* __restrict__ W_g, const float* __restrict__ b_g,
                 float* __restrict__ r_out,
                 float* __restrict__ h_new, float* __restrict__ c_new,
                 bf16* __restrict__ hh, bf16* __restrict__ hl)
{
    const int b   = blockIdx.x;
    const int tid = threadIdx.x;
    __shared__ float sh_h[SS], sh_c[SS];
    __shared__ float s0[256], s1[256];
    __shared__ float r0sh;

    // ---- small LSTM activation (writes smem + global)
    const float* gs = Gs + (size_t)b * (4 * SS);
    for (int n = tid; n < SS; n += 256) {
        float i_ = sigf(gs[n]);
        float f_ = sigf(gs[SS + n]);
        float gg = tanhf(gs[2 * SS + n]);
        float o_ = sigf(gs[3 * SS + n]);
        float c2 = f_ * cs_old[(size_t)b * SS + n] + i_ * gg;
        float h2 = o_ * tanhf(c2);
        sh_h[n] = h2; sh_c[n] = c2;
        cs_new[(size_t)b * SS + n] = c2;
        hs_new[(size_t)b * SS + n] = h2;
        split1(h2, hsh, hsl, (size_t)b * SS + n);
    }

    // ---- hard gate on OLD large state: r = one_hot(argmax(p))
    const float* s = sfeats + ((size_t)b * TT + t) * SS;
    const float* h = h_old + (size_t)b * LL;
    const float* c = c_old + (size_t)b * LL;
    const float* w0 = W_g;
    const float* w1 = W_g + 2560;
    float p0 = 0.f, p1 = 0.f;
    for (int j = tid; j < SS; j += 256) { float v = s[j]; p0 += v * w0[j]; p1 += v * w1[j]; }
    for (int j = tid; j < LL; j += 256) { float v = h[j]; p0 += v * w0[SS + j]; p1 += v * w1[SS + j]; }
    for (int j = tid; j < LL; j += 256) { float v = c[j]; p0 += v * w0[SS + LL + j]; p1 += v * w1[SS + LL + j]; }
    s0[tid] = p0; s1[tid] = p1;
    __syncthreads();                       // also publishes sh_h/sh_c
    for (int st = 128; st > 0; st >>= 1) {
        if (tid < st) { s0[tid] += s0[tid + st]; s1[tid] += s1[tid + st]; }
        __syncthreads();
    }
    if (tid == 0) {
        float r0 = (s0[0] + b_g[0] >= s1[0] + b_g[1]) ? 1.f : 0.f;
        r0sh = r0;
        r_out[b * 2 + 0] = r0;
        r_out[b * 2 + 1] = 1.f - r0;
    }
    __syncthreads();
    const float r0 = r0sh, r1 = 1.f - r0sh;

    // ---- large LSTM activation + straight-through merge
    const float* g = Gl + (size_t)b * (4 * LL);
    for (int n = tid; n < LL; n += 256) {
        size_t idx = (size_t)b * LL + n;
        float i_ = sigf(g[n]);
        float f_ = sigf(g[LL + n]);
        float gg = tanhf(g[2 * LL + n]);
        float o_ = sigf(g[3 * LL + n]);
        float c_ln = f_ * c_old[idx] + i_ * gg;
        float h_ln = o_ * tanhf(c_ln);
        float ph = (n < SS) ? sh_h[n] : h_old[idx];
        float pc = (n < SS) ? sh_c[n] : c_old[idx];
        float h2 = r0 * h_ln + r1 * ph;
        c_new[idx] = r0 * c_ln + r1 * pc;
        h_new[idx] = h2;
        split1(h2, hh, hl, idx);
    }
}

// ---------------------------------------------------------------------------
// Launch
// ---------------------------------------------------------------------------
static inline float* fsym(const void* s) { void* p = nullptr; cudaGetSymbolAddress(&p, s); return (float*)p; }
static inline bf16*  bsym(const void* s) { void* p = nullptr; cudaGetSymbolAddress(&p, s); return (bf16*)p; }

extern "C" void kernel_launch(void* const* d_in, const int* in_sizes, int n_in,
                              void* d_out, int out_size)
{
    const float* x     = (const float*)d_in[0];
    const float* xs    = (const float*)d_in[1];
    const float* W_p   = (const float*)d_in[2];
    const float* b_p   = (const float*)d_in[3];
    const float* g_p   = (const float*)d_in[4];
    const float* be_p  = (const float*)d_in[5];
    const float* W_s   = (const float*)d_in[6];
    const float* b_s   = (const float*)d_in[7];
    const float* g_s   = (const float*)d_in[8];
    const float* be_s  = (const float*)d_in[9];
    const float* Wih_l = (const float*)d_in[10];
    const float* Whh_l = (const float*)d_in[11];
    const float* bih_l = (const float*)d_in[12];
    const float* bhh_l = (const float*)d_in[13];
    const float* Wih_s = (const float*)d_in[14];
    const float* Whh_s = (const float*)d_in[15];
    const float* bih_s = (const float*)d_in[16];
    const float* bhh_s = (const float*)d_in[17];
    const float* W_g   = (const float*)d_in[18];
    const float* b_g   = (const float*)d_in[19];
    const float* W_c   = (const float*)d_in[20];
    const float* b_c   = (const float*)d_in[21];

    float* out = (float*)d_out;
    float* out_logits = out;
    float* out_r      = out + BB * NCLS;

    bf16 *xh = bsym(g_x_hi), *xl = bsym(g_x_lo);
    bf16 *xsh = bsym(g_xs_hi), *xsl = bsym(g_xs_lo);
    bf16 *fh = bsym(g_f_hi), *fl = bsym(g_f_lo);
    bf16 *sfh = bsym(g_sf_hi), *sfl = bsym(g_sf_lo);
    bf16 *Wph = bsym(g_Wp_hi), *Wpl = bsym(g_Wp_lo);
    bf16 *Wsh = bsym(g_Ws_hi), *Wsl = bsym(g_Ws_lo);
    bf16 *Wlh = bsym(g_Wl_hi), *Wll = bsym(g_Wl_lo);
    bf16 *Whlh = bsym(g_Whl_hi), *Whll = bsym(g_Whl_lo);
    bf16 *Wish = bsym(g_Wis_hi), *Wisl = bsym(g_Wis_lo);
    bf16 *Whsh = bsym(g_Whs_hi), *Whsl = bsym(g_Whs_lo);
    bf16 *Wch = bsym(g_Wc_hi), *Wcl = bsym(g_Wc_lo);

    float* sfeats = fsym(g_sfeats);
    float* sgpre  = fsym(g_sgpre);
    float* lgpre  = fsym(g_lgpre);
    float* Gs = fsym(g_Gs);
    float* Gl = fsym(g_Gl);
    float* hl = fsym(g_hl);
    float* cl = fsym(g_cl);
    float* hs = fsym(g_hs);
    float* cs = fsym(g_cs);
    bf16* hlh = bsym(g_hl_hi); bf16* hll = bsym(g_hl_lo);
    bf16* hsh = bsym(g_hs_hi); bf16* hsl = bsym(g_hs_lo);

    cudaFuncSetAttribute(gemm3_kernel, cudaFuncAttributeMaxDynamicSharedMemorySize, GSMEM);
    cudaFuncSetAttribute(step_gemm_kernel, cudaFuncAttributeMaxDynamicSharedMemorySize, GSMEM);

    const int TPB = 256;

    // ---- fused split of all inputs & weights into bf16 pairs
    {
        SJobs jb;
        const float* srcs[9] = { x, xs, W_p, W_s, Wih_l, Whh_l, Wih_s, Whh_s, W_c };
        bf16* his[9] = { xh, xsh, Wph, Wsh, Wlh, Whlh, Wish, Whsh, Wch };
        bf16* los[9] = { xl, xsl, Wpl, Wsl, Wll, Whll, Wisl, Whsl, Wcl };
        long  ns [9] = { (long)MBT * 2048, (long)MBT * 1280, 2048L * 2048, 512L * 1280,
                         4096L * 2560, 4096L * 1024, 2048L * 512, 2048L * 512,
                         (long)NCLS * 1024 };
        unsigned cum = 0;
        for (int k = 0; k < 9; k++) {
            jb.j[k].src = (const float4*)srcs[k];
            jb.j[k].hi  = (__nv_bfloat162*)his[k];
            jb.j[k].lo  = (__nv_bfloat162*)los[k];
            jb.cum[k] = cum;
            cum += (unsigned)(ns[k] / 4);
        }
        jb.cum[9] = cum;
        split_all_kernel<<<(cum + TPB - 1) / TPB, TPB>>>(jb, cum);
    }
    zero_states_kernel<<<(BB * LL + 255) / 256, TPB>>>(hl, cl, hs, cs, hlh, hll, hsh, hsl);

    // ---- Phase 1: time-parallel GEMMs
    // feats(split) = relu(BN(x @ W_p^T + b_p))
    gemm3_kernel<<<dim3(2048 / 128, MBT / 128), 256, GSMEM>>>(
        xh, xl, 2048, nullptr, nullptr, 0, 2048,
        Wph, Wpl, 2048, 2048, 2048,
        b_p, nullptr, nullptr, 0, g_p, be_p,
        nullptr, 0, fh, fl, 2048);
    // sfeats(fp32+split) = relu(BN(xs @ W_s^T + b_s))
    gemm3_kernel<<<dim3(512 / 128, MBT / 128), 256, GSMEM>>>(
        xsh, xsl, 1280, nullptr, nullptr, 0, 1280,
        Wsh, Wsl, 1280, 512, 1280,
        b_s, nullptr, nullptr, 0, g_s, be_s,
        sfeats, 512, sfh, sfl, 512);
    // sgpre = sfeats @ Wih_s^T + bih_s + bhh_s
    gemm3_kernel<<<dim3(2048 / 128, MBT / 128), 256, GSMEM>>>(
        sfh, sfl, 512, nullptr, nullptr, 0, 512,
        Wish, Wisl, 512, 2048, 512,
        bih_s, bhh_s, nullptr, 0, nullptr, nullptr,
        sgpre, 2048, nullptr, nullptr, 0);
    // lgpre = [feats, sfeats] @ Wih_l^T + bih_l + bhh_l   (K-concat 2048+512)
    gemm3_kernel<<<dim3(4096 / 128, MBT / 128), 256, GSMEM>>>(
        fh, fl, 2048, sfh, sfl, 512, 2048,
        Wlh, Wll, 2560, 4096, 2560,
        bih_l, bhh_l, nullptr, 0, nullptr, nullptr,
        lgpre, 4096, nullptr, nullptr, 0);

    // ---- Phase 2: recurrence (2 launches per step)
    for (int t = 0; t < TT; t++) {
        int cur = t & 1, nxt = 1 - cur;
        float* hl_c = hl + (size_t)cur * BB * LL;
        float* cl_c = cl + (size_t)cur * BB * LL;
        float* hl_n = hl + (size_t)nxt * BB * LL;
        float* cl_n = cl + (size_t)nxt * BB * LL;
        float* cs_c = cs + (size_t)cur * BB * SS;
        float* hs_n = hs + (size_t)nxt * BB * SS;
        float* cs_n = cs + (size_t)nxt * BB * SS;
        bf16* hlh_c = hlh + (size_t)cur * BB * LL;
        bf16* hll_c = hll + (size_t)cur * BB * LL;
        bf16* hlh_n = hlh + (size_t)nxt * BB * LL;
        bf16* hll_n = hll + (size_t)nxt * BB * LL;
        bf16* hsh_c = hsh + (size_t)cur * BB * SS;
        bf16* hsl_c = hsl + (size_t)cur * BB * SS;
        bf16* hsh_n = hsh + (size_t)nxt * BB * SS;
        bf16* hsl_n = hsl + (size_t)nxt * BB * SS;
        float* r_t = out_r + (size_t)t * BB * 2;

        step_gemm_kernel<<<dim3(4096 / 128, BB / 128, 2), 256, GSMEM>>>(
            hsh_c, hsl_c, Whsh, Whsl, sgpre + (size_t)t * 2048,
            hlh_c, hll_c, Whlh, Whll, lgpre + (size_t)t * 4096,
            Gs, Gl);
        step_post_kernel<<<BB, 256>>>(
            Gs, Gl, sfeats, t, hl_c, cl_c, cs_c,
            hs_n, cs_n, hsh_n, hsl_n,
            W_g, b_g, r_t, hl_n, cl_n, hlh_n, hll_n);
    }

    // ---- classifier on final h_l (buffer 0 after 64 steps)
    gemm3_kernel<<<dim3((NCLS + 127) / 128, BB / 128), 256, GSMEM>>>(
        hlh, hll, 1024, nullptr, nullptr, 0, 1024,
        Wch, Wcl, 1024, NCLS, 1024,
        b_c, nullptr, nullptr, 0, nullptr, nullptr,
        out_logits, NCLS, nullptr, nullptr, 0);
}

// round 6
// speedup vs baseline: 2.0996x; 1.0428x over previous
#include <cuda_runtime.h>
#include <cuda_bf16.h>
#include <math.h>
#include <stdint.h>

// ---------------------------------------------------------------------------
// Problem constants
// ---------------------------------------------------------------------------
#define BB 256
#define TT 64
#define LL 1024
#define SS 512
#define NCLS 239
#define MBT (BB * TT)          // 16384

typedef __nv_bfloat16 bf16;

// ---------------------------------------------------------------------------
// Scratch (device globals; no runtime allocation allowed)
// ---------------------------------------------------------------------------
__device__ bf16 g_x_hi  [MBT * 2048];
__device__ bf16 g_x_lo  [MBT * 2048];
__device__ bf16 g_xs_hi [MBT * 1280];
__device__ bf16 g_xs_lo [MBT * 1280];
__device__ bf16 g_f_hi  [MBT * 2048];
__device__ bf16 g_f_lo  [MBT * 2048];
__device__ bf16 g_sf_hi [MBT * 512];
__device__ bf16 g_sf_lo [MBT * 512];
__device__ bf16 g_Wp_hi [2048 * 2048];
__device__ bf16 g_Wp_lo [2048 * 2048];
__device__ bf16 g_Ws_hi [512 * 1280];
__device__ bf16 g_Ws_lo [512 * 1280];
__device__ bf16 g_Wl_hi [4096 * 2560];   // Wih_l full (K-concat GEMM)
__device__ bf16 g_Wl_lo [4096 * 2560];
__device__ bf16 g_Whl_hi[4096 * 1024];   // Whh_l
__device__ bf16 g_Whl_lo[4096 * 1024];
__device__ bf16 g_Wis_hi[2048 * 512];    // Wih_s
__device__ bf16 g_Wis_lo[2048 * 512];
__device__ bf16 g_Whs_hi[2048 * 512];    // Whh_s
__device__ bf16 g_Whs_lo[2048 * 512];
__device__ bf16 g_Wc_hi [NCLS * 1024];
__device__ bf16 g_Wc_lo [NCLS * 1024];
__device__ float g_sfeats[MBT * 512];
__device__ float g_sgpre [MBT * 2048];
__device__ float g_lgpre [MBT * 4096];
__device__ float g_Gs [BB * 2048];
__device__ float g_GlA[BB * 4096];       // Gl K-half 0 (+ lgpre addsrc)
__device__ float g_GlB[BB * 4096];       // Gl K-half 1
__device__ float g_hl[2][BB * LL];
__device__ float g_cl[2][BB * LL];
__device__ float g_hs[2][BB * SS];
__device__ float g_cs[2][BB * SS];
__device__ bf16 g_hl_hi[2][BB * LL];
__device__ bf16 g_hl_lo[2][BB * LL];
__device__ bf16 g_hs_hi[2][BB * SS];
__device__ bf16 g_hs_lo[2][BB * SS];

// ---------------------------------------------------------------------------
// PTX helpers (legacy tensor path only — harness targets compute_100)
// ---------------------------------------------------------------------------
__device__ __forceinline__ uint32_t smem_u32(const void* p) {
    return (uint32_t)__cvta_generic_to_shared(p);
}
__device__ __forceinline__ void cp16(uint32_t dst, const void* src, int srcsize) {
    asm volatile("cp.async.cg.shared.global [%0], [%1], 16, %2;\n"
                 :: "r"(dst), "l"(src), "r"(srcsize));
}
__device__ __forceinline__ void cp_commit() {
    asm volatile("cp.async.commit_group;\n");
}
template<int N>
__device__ __forceinline__ void cp_wait() {
    asm volatile("cp.async.wait_group %0;\n" :: "n"(N));
}
__device__ __forceinline__ void ldsm4(uint32_t* r, uint32_t addr) {
    asm volatile("ldmatrix.sync.aligned.m8n8.x4.shared.b16 {%0,%1,%2,%3}, [%4];\n"
                 : "=r"(r[0]), "=r"(r[1]), "=r"(r[2]), "=r"(r[3]) : "r"(addr));
}
__device__ __forceinline__ void mma_bf16(float* d, const uint32_t* a, uint32_t b0, uint32_t b1) {
    asm volatile("mma.sync.aligned.m16n8k16.row.col.f32.bf16.bf16.f32 "
                 "{%0,%1,%2,%3},{%4,%5,%6,%7},{%8,%9},{%0,%1,%2,%3};\n"
                 : "+f"(d[0]), "+f"(d[1]), "+f"(d[2]), "+f"(d[3])
                 : "r"(a[0]), "r"(a[1]), "r"(a[2]), "r"(a[3]), "r"(b0), "r"(b1));
}

// ---------------------------------------------------------------------------
// Split-bf16 triple-product GEMM core (4-stage cp.async pipeline).
//   C[M,N] = epi( A@W^T ), A = A_hi+A_lo, W = W_hi+W_lo, computed as
//   Ahi*Whi + Ahi*Wlo + Alo*Whi. A may be a K-concat: cols [0,K1) from A,
//   [K1,K) from A2 (K1 % 32 == 0). BM=BN=128, 256 threads, K % 32 == 0.
//   cp.async issues for stage s+3 are interleaved into the ks-loop of stage s
//   (A-half with ks=0, B-half with ks=16) to avoid post-barrier MIO bursts.
// ---------------------------------------------------------------------------
#define LDSH 40                       // halves per smem row (padded)
#define GSMEM (8 * 128 * LDSH * 2)    // 4 stages * (A + B) = 81920 bytes

__device__ __forceinline__ void gemm_core(
    char* smem, int bx, int by,
    const bf16* __restrict__ Ahi, const bf16* __restrict__ Alo, int lda,
    const bf16* __restrict__ A2hi, const bf16* __restrict__ A2lo, int lda2, int K1,
    const bf16* __restrict__ Bhi, const bf16* __restrict__ Blo, int ldb,
    int N, int K,
    const float* __restrict__ b1, const float* __restrict__ b2,
    const float* __restrict__ addsrc, int ldadd,
    const float* __restrict__ gamma, const float* __restrict__ beta,
    float* __restrict__ Cf, int ldc,
    bf16* __restrict__ Chi, bf16* __restrict__ Clo, int ldsp)
{
    constexpr int BM = 128, BN = 128, NT = 256;
    const int tid  = threadIdx.x;
    const int lane = tid & 31;
    const int wid  = tid >> 5;
    const int wm   = wid >> 2;          // 2 warp rows (64 each)
    const int wn   = wid & 3;           // 4 warp cols (32 each)
    const int bm   = by * BM;
    const int bn   = bx * BN;

    const int NK = K / 32;
    const int NS = 3 * NK;

    float acc[4][4][4];
#pragma unroll
    for (int i = 0; i < 4; i++)
#pragma unroll
        for (int j = 0; j < 4; j++)
#pragma unroll
            for (int r = 0; r < 4; r++) acc[i][j][r] = 0.f;

    auto stageA = [&](int s) {
        int p  = s / NK;
        int k0 = (s - p * NK) * 32;
        const bf16* Ap; int ald, ak;
        if (k0 < K1) { Ap = (p == 2) ? Alo  : Ahi;  ald = lda;  ak = k0; }
        else         { Ap = (p == 2) ? A2lo : A2hi; ald = lda2; ak = k0 - K1; }
        uint32_t ab = smem_u32(smem) + (s & 3) * (BM * LDSH * 2);
#pragma unroll
        for (int v = tid; v < BM * 4; v += NT) {
            int row = v >> 2, kc = (v & 3) * 8;
            cp16(ab + (row * LDSH + kc) * 2,
                 Ap + (size_t)(bm + row) * ald + ak + kc, 16);
        }
    };
    auto stageB = [&](int s) {
        int p  = s / NK;
        int k0 = (s - p * NK) * 32;
        const bf16* Bp = (p == 1) ? Blo : Bhi;
        uint32_t bb = smem_u32(smem) + (4 + (s & 3)) * (BM * LDSH * 2);
#pragma unroll
        for (int v = tid; v < BN * 4; v += NT) {
            int row = v >> 2, kc = (v & 3) * 8;
            int n = bn + row;
            bool ok = (n < N);
            cp16(bb + (row * LDSH + kc) * 2,
                 Bp + (size_t)(ok ? n : 0) * ldb + k0 + kc, ok ? 16 : 0);
        }
    };

    stageA(0); stageB(0); cp_commit();
    if (NS > 1) { stageA(1); stageB(1); }
    cp_commit();
    if (NS > 2) { stageA(2); stageB(2); }
    cp_commit();

    for (int s = 0; s < NS; s++) {
        cp_wait<2>();
        __syncthreads();   // stage s data landed; prior reads of buffer (s+3)&3 done
        const bool pf = (s + 3 < NS);

        uint32_t asb = smem_u32(smem) + (s & 3) * (BM * LDSH * 2);
        uint32_t bsb = smem_u32(smem) + (4 + (s & 3)) * (BM * LDSH * 2);
#pragma unroll
        for (int ks2 = 0; ks2 < 2; ks2++) {
            const int ks = ks2 * 16;
            uint32_t a[4][4], b[4][2];
#pragma unroll
            for (int mi = 0; mi < 4; mi++) {
                int row = wm * 64 + mi * 16 + (lane & 15);
                int kk  = ks + (lane >> 4) * 8;
                ldsm4(a[mi], asb + (row * LDSH + kk) * 2);
            }
#pragma unroll
            for (int ng = 0; ng < 2; ng++) {
                int row = wn * 32 + ng * 16 + (lane & 7) + ((lane >> 4) << 3);
                int kk  = ks + (((lane >> 3) & 1) << 3);
                uint32_t t[4];
                ldsm4(t, bsb + (row * LDSH + kk) * 2);
                b[2 * ng][0] = t[0]; b[2 * ng][1] = t[1];
                b[2 * ng + 1][0] = t[2]; b[2 * ng + 1][1] = t[3];
            }
            // interleave next-stage cp.async issues under the MMA block
            if (pf) { if (ks2 == 0) stageA(s + 3); else stageB(s + 3); }
#pragma unroll
            for (int mi = 0; mi < 4; mi++)
#pragma unroll
                for (int nj = 0; nj < 4; nj++)
                    mma_bf16(acc[mi][nj], a[mi], b[nj][0], b[nj][1]);
        }
        cp_commit();
    }

    // ---- epilogue (register-resident)
    const float inv_std = rsqrtf(1.0f + 1e-5f);
    const int g  = lane >> 2;
    const int tg = lane & 3;
#pragma unroll
    for (int mi = 0; mi < 4; mi++)
#pragma unroll
        for (int nj = 0; nj < 4; nj++)
#pragma unroll
            for (int r = 0; r < 4; r++) {
                int m = bm + wm * 64 + mi * 16 + g + ((r >> 1) << 3);
                int n = bn + wn * 32 + nj * 8 + tg * 2 + (r & 1);
                if (n >= N) continue;
                float v = acc[mi][nj][r];
                if (b1)     v += b1[n];
                if (b2)     v += b2[n];
                if (addsrc) v += addsrc[(size_t)m * ldadd + n];
                if (gamma)  v = fmaxf(0.f, v * (gamma[n] * inv_std) + beta[n]);
                if (Cf)     Cf[(size_t)m * ldc + n] = v;
                if (Chi) {
                    bf16 h = __float2bfloat16(v);
                    Chi[(size_t)m * ldsp + n] = h;
                    Clo[(size_t)m * ldsp + n] = __float2bfloat16(v - __bfloat162float(h));
                }
            }
}

// standalone GEMM launcher (2 CTAs/SM)
__global__ void __launch_bounds__(256, 2)
gemm3_kernel(const bf16* Ahi, const bf16* Alo, int lda,
             const bf16* A2hi, const bf16* A2lo, int lda2, int K1,
             const bf16* Bhi, const bf16* Blo, int ldb,
             int N, int K,
             const float* b1, const float* b2,
             const float* addsrc, int ldadd,
             const float* gamma, const float* beta,
             float* Cf, int ldc,
             bf16* Chi, bf16* Clo, int ldsp)
{
    extern __shared__ char smem[];
    gemm_core(smem, blockIdx.x, blockIdx.y,
              Ahi, Alo, lda, A2hi, A2lo, lda2, K1, Bhi, Blo, ldb, N, K,
              b1, b2, addsrc, ldadd, gamma, beta, Cf, ldc, Chi, Clo, ldsp);
}

// fused per-step GEMM with split-K on Gl:
//   z==0 -> Gs   (N=2048, K=512, addsrc=sgpre_t)     [x < 16]
//   z==1 -> GlA  (N=4096, K=[0,512),  addsrc=lgpre_t)
//   z==2 -> GlB  (N=4096, K=[512,1024), no addsrc)
__global__ void __launch_bounds__(256, 2)
step_gemm_kernel(const bf16* hsh, const bf16* hsl, const bf16* Whsh, const bf16* Whsl,
                 const float* sgpre_t,
                 const bf16* hlh, const bf16* hll, const bf16* Whlh, const bf16* Whll,
                 const float* lgpre_t,
                 float* Gs, float* GlA, float* GlB)
{
    extern __shared__ char smem[];
    if (blockIdx.z == 0) {
        if (blockIdx.x >= 2048 / 128) return;
        gemm_core(smem, blockIdx.x, blockIdx.y,
                  hsh, hsl, 512, nullptr, nullptr, 0, 512,
                  Whsh, Whsl, 512, 2048, 512,
                  nullptr, nullptr, sgpre_t, TT * 2048, nullptr, nullptr,
                  Gs, 2048, nullptr, nullptr, 0);
    } else if (blockIdx.z == 1) {
        gemm_core(smem, blockIdx.x, blockIdx.y,
                  hlh, hll, 1024, nullptr, nullptr, 0, 1024,
                  Whlh, Whll, 1024, 4096, 512,
                  nullptr, nullptr, lgpre_t, TT * 4096, nullptr, nullptr,
                  GlA, 4096, nullptr, nullptr, 0);
    } else {
        gemm_core(smem, blockIdx.x, blockIdx.y,
                  hlh + 512, hll + 512, 1024, nullptr, nullptr, 0, 1024,
                  Whlh + 512, Whll + 512, 1024, 4096, 512,
                  nullptr, nullptr, nullptr, 0, nullptr, nullptr,
                  GlB, 4096, nullptr, nullptr, 0);
    }
}

// ---------------------------------------------------------------------------
// Elementwise kernels
// ---------------------------------------------------------------------------
__device__ __forceinline__ float sigf(float x) { return 1.f / (1.f + expf(-x)); }
__device__ __forceinline__ void split1(float v, bf16* hi, bf16* lo, size_t i) {
    bf16 h = __float2bfloat16(v);
    hi[i] = h;
    lo[i] = __float2bfloat16(v - __bfloat162float(h));
}

// one fused split kernel over all 9 tensors (float4-vectorized, grid-stride)
struct SJob { const float4* src; __nv_bfloat162* hi; __nv_bfloat162* lo; };
struct SJobs { SJob j[9]; unsigned cum[10]; };

__global__ void __launch_bounds__(256)
split_all_kernel(SJobs jb, unsigned total4)
{
    const unsigned stride = gridDim.x * blockDim.x;
    for (unsigned i = blockIdx.x * blockDim.x + threadIdx.x; i < total4; i += stride) {
        int k = 0;
#pragma unroll
        for (int q = 0; q < 8; q++) if (i >= jb.cum[q + 1]) k = q + 1;
        unsigned off = i - jb.cum[k];
        float4 v = jb.j[k].src[off];
        bf16 h0 = __float2bfloat16(v.x), h1 = __float2bfloat16(v.y);
        bf16 h2 = __float2bfloat16(v.z), h3 = __float2bfloat16(v.w);
        bf16 l0 = __float2bfloat16(v.x - __bfloat162float(h0));
        bf16 l1 = __float2bfloat16(v.y - __bfloat162float(h1));
        bf16 l2 = __float2bfloat16(v.z - __bfloat162float(h2));
        bf16 l3 = __float2bfloat16(v.w - __bfloat162float(h3));
        jb.j[k].hi[2 * off]     = __nv_bfloat162(h0, h1);
        jb.j[k].hi[2 * off + 1] = __nv_bfloat162(h2, h3);
        jb.j[k].lo[2 * off]     = __nv_bfloat162(l0, l1);
        jb.j[k].lo[2 * off + 1] = __nv_bfloat162(l2, l3);
    }
}

__global__ void zero_states_kernel(float* hl, float* cl, float* hs, float* cs,
                                   bf16* hlh, bf16* hll, bf16* hsh, bf16* hsl)
{
    int i = blockIdx.x * blockDim.x + threadIdx.x;
    if (i < BB * LL) { hl[i] = 0.f; cl[i] = 0.f; hlh[i] = __float2bfloat16(0.f); hll[i] = __float2bfloat16(0.f); }
    if (i < BB * SS) { hs[i] = 0.f; cs[i] = 0.f; hsh[i] = __float2bfloat16(0.f); hsl[i] = __float2bfloat16(0.f); }
}

// fused per-step post-GEMM kernel: small LSTM act + hard gate + large act/merge.
// One block per batch row. Gl = GlA + GlB (split-K halves).
__global__ void __launch_bounds__(256)
step_post_kernel(const float* __restrict__ Gs,
                 const float* __restrict__ GlA, const float* __restrict__ GlB,
                 const float* __restrict__ sfeats, int t,
                 const float* __restrict__ h_old, const float* __restrict__ c_old,
                 const float* __restrict__ cs_old,
                 float* __restrict__ hs_new, float* __restrict__ cs_new,
                 bf16* __restrict__ hsh, bf16* __restrict__ hsl,
                 const float* __restrict__ W_g, const float* __restrict__ b_g,
                 float* __restrict__ r_out,
                 float* __restrict__ h_new, float* __restrict__ c_new,
                 bf16* __restrict__ hh, bf16* __restrict__ hl)
{
    const int b   = blockIdx.x;
    const int tid = threadIdx.x;
    __shared__ float sh_h[SS], sh_c[SS];
    __shared__ float s0[256], s1[256];
    __shared__ float r0sh;

    // ---- small LSTM activation (writes smem + global)
    const float* gs = Gs + (size_t)b * (4 * SS);
    for (int n = tid; n < SS; n += 256) {
        float i_ = sigf(gs[n]);
        float f_ = sigf(gs[SS + n]);
        float gg = tanhf(gs[2 * SS + n]);
        float o_ = sigf(gs[3 * SS + n]);
        float c2 = f_ * cs_old[(size_t)b * SS + n] + i_ * gg;
        float h2 = o_ * tanhf(c2);
        sh_h[n] = h2; sh_c[n] = c2;
        cs_new[(size_t)b * SS + n] = c2;
        hs_new[(size_t)b * SS + n] = h2;
        split1(h2, hsh, hsl, (size_t)b * SS + n);
    }

    // ---- hard gate on OLD large state: r = one_hot(argmax(p))
    const float* s = sfeats + ((size_t)b * TT + t) * SS;
    const float* h = h_old + (size_t)b * LL;
    const float* c = c_old + (size_t)b * LL;
    const float* w0 = W_g;
    const float* w1 = W_g + 2560;
    float p0 = 0.f, p1 = 0.f;
    for (int j = tid; j < SS; j += 256) { float v = s[j]; p0 += v * w0[j]; p1 += v * w1[j]; }
    for (int j = tid; j < LL; j += 256) { float v = h[j]; p0 += v * w0[SS + j]; p1 += v * w1[SS + j]; }
    for (int j = tid; j < LL; j += 256) { float v = c[j]; p0 += v * w0[SS + LL + j]; p1 += v * w1[SS + LL + j]; }
    s0[tid] = p0; s1[tid] = p1;
    __syncthreads();                       // also publishes sh_h/sh_c
    for (int st = 128; st > 0; st >>= 1) {
        if (tid < st) { s0[tid] += s0[tid + st]; s1[tid] += s1[tid + st]; }
        __syncthreads();
    }
    if (tid == 0) {
        float r0 = (s0[0] + b_g[0] >= s1[0] + b_g[1]) ? 1.f : 0.f;
        r0sh = r0;
        r_out[b * 2 + 0] = r0;
        r_out[b * 2 + 1] = 1.f - r0;
    }
    __syncthreads();
    const float r0 = r0sh, r1 = 1.f - r0sh;

    // ---- large LSTM activation + straight-through merge
    const float* gA = GlA + (size_t)b * (4 * LL);
    const float* gB = GlB + (size_t)b * (4 * LL);
    for (int n = tid; n < LL; n += 256) {
        size_t idx = (size_t)b * LL + n;
        float i_ = sigf(gA[n] + gB[n]);
        float f_ = sigf(gA[LL + n] + gB[LL + n]);
        float gg = tanhf(gA[2 * LL + n] + gB[2 * LL + n]);
        float o_ = sigf(gA[3 * LL + n] + gB[3 * LL + n]);
        float c_ln = f_ * c_old[idx] + i_ * gg;
        float h_ln = o_ * tanhf(c_ln);
        float ph = (n < SS) ? sh_h[n] : h_old[idx];
        float pc = (n < SS) ? sh_c[n] : c_old[idx];
        float h2 = r0 * h_ln + r1 * ph;
        c_new[idx] = r0 * c_ln + r1 * pc;
        h_new[idx] = h2;
        split1(h2, hh, hl, idx);
    }
}

// ---------------------------------------------------------------------------
// Launch
// ---------------------------------------------------------------------------
static inline float* fsym(const void* s) { void* p = nullptr; cudaGetSymbolAddress(&p, s); return (float*)p; }
static inline bf16*  bsym(const void* s) { void* p = nullptr; cudaGetSymbolAddress(&p, s); return (bf16*)p; }

extern "C" void kernel_launch(void* const* d_in, const int* in_sizes, int n_in,
                              void* d_out, int out_size)
{
    const float* x     = (const float*)d_in[0];
    const float* xs    = (const float*)d_in[1];
    const float* W_p   = (const float*)d_in[2];
    const float* b_p   = (const float*)d_in[3];
    const float* g_p   = (const float*)d_in[4];
    const float* be_p  = (const float*)d_in[5];
    const float* W_s   = (const float*)d_in[6];
    const float* b_s   = (const float*)d_in[7];
    const float* g_s   = (const float*)d_in[8];
    const float* be_s  = (const float*)d_in[9];
    const float* Wih_l = (const float*)d_in[10];
    const float* Whh_l = (const float*)d_in[11];
    const float* bih_l = (const float*)d_in[12];
    const float* bhh_l = (const float*)d_in[13];
    const float* Wih_s = (const float*)d_in[14];
    const float* Whh_s = (const float*)d_in[15];
    const float* bih_s = (const float*)d_in[16];
    const float* bhh_s = (const float*)d_in[17];
    const float* W_g   = (const float*)d_in[18];
    const float* b_g   = (const float*)d_in[19];
    const float* W_c   = (const float*)d_in[20];
    const float* b_c   = (const float*)d_in[21];

    float* out = (float*)d_out;
    float* out_logits = out;
    float* out_r      = out + BB * NCLS;

    bf16 *xh = bsym(g_x_hi), *xl = bsym(g_x_lo);
    bf16 *xsh = bsym(g_xs_hi), *xsl = bsym(g_xs_lo);
    bf16 *fh = bsym(g_f_hi), *fl = bsym(g_f_lo);
    bf16 *sfh = bsym(g_sf_hi), *sfl = bsym(g_sf_lo);
    bf16 *Wph = bsym(g_Wp_hi), *Wpl = bsym(g_Wp_lo);
    bf16 *Wsh = bsym(g_Ws_hi), *Wsl = bsym(g_Ws_lo);
    bf16 *Wlh = bsym(g_Wl_hi), *Wll = bsym(g_Wl_lo);
    bf16 *Whlh = bsym(g_Whl_hi), *Whll = bsym(g_Whl_lo);
    bf16 *Wish = bsym(g_Wis_hi), *Wisl = bsym(g_Wis_lo);
    bf16 *Whsh = bsym(g_Whs_hi), *Whsl = bsym(g_Whs_lo);
    bf16 *Wch = bsym(g_Wc_hi), *Wcl = bsym(g_Wc_lo);

    float* sfeats = fsym(g_sfeats);
    float* sgpre  = fsym(g_sgpre);
    float* lgpre  = fsym(g_lgpre);
    float* Gs  = fsym(g_Gs);
    float* GlA = fsym(g_GlA);
    float* GlB = fsym(g_GlB);
    float* hl = fsym(g_hl);
    float* cl = fsym(g_cl);
    float* hs = fsym(g_hs);
    float* cs = fsym(g_cs);
    bf16* hlh = bsym(g_hl_hi); bf16* hll = bsym(g_hl_lo);
    bf16* hsh = bsym(g_hs_hi); bf16* hsl = bsym(g_hs_lo);

    cudaFuncSetAttribute(gemm3_kernel, cudaFuncAttributeMaxDynamicSharedMemorySize, GSMEM);
    cudaFuncSetAttribute(step_gemm_kernel, cudaFuncAttributeMaxDynamicSharedMemorySize, GSMEM);

    const int TPB = 256;

    // ---- fused split of all inputs & weights into bf16 pairs
    {
        SJobs jb;
        const float* srcs[9] = { x, xs, W_p, W_s, Wih_l, Whh_l, Wih_s, Whh_s, W_c };
        bf16* his[9] = { xh, xsh, Wph, Wsh, Wlh, Whlh, Wish, Whsh, Wch };
        bf16* los[9] = { xl, xsl, Wpl, Wsl, Wll, Whll, Wisl, Whsl, Wcl };
        long  ns [9] = { (long)MBT * 2048, (long)MBT * 1280, 2048L * 2048, 512L * 1280,
                         4096L * 2560, 4096L * 1024, 2048L * 512, 2048L * 512,
                         (long)NCLS * 1024 };
        unsigned cum = 0;
        for (int k = 0; k < 9; k++) {
            jb.j[k].src = (const float4*)srcs[k];
            jb.j[k].hi  = (__nv_bfloat162*)his[k];
            jb.j[k].lo  = (__nv_bfloat162*)los[k];
            jb.cum[k] = cum;
            cum += (unsigned)(ns[k] / 4);
        }
        jb.cum[9] = cum;
        int grid = (int)((cum / 2 + TPB - 1) / TPB);     // 2 float4 per thread
        split_all_kernel<<<grid, TPB>>>(jb, cum);
    }
    zero_states_kernel<<<(BB * LL + 255) / 256, TPB>>>(hl, cl, hs, cs, hlh, hll, hsh, hsl);

    // ---- Phase 1: time-parallel GEMMs
    // feats(split) = relu(BN(x @ W_p^T + b_p))
    gemm3_kernel<<<dim3(2048 / 128, MBT / 128), 256, GSMEM>>>(
        xh, xl, 2048, nullptr, nullptr, 0, 2048,
        Wph, Wpl, 2048, 2048, 2048,
        b_p, nullptr, nullptr, 0, g_p, be_p,
        nullptr, 0, fh, fl, 2048);
    // sfeats(fp32+split) = relu(BN(xs @ W_s^T + b_s))
    gemm3_kernel<<<dim3(512 / 128, MBT / 128), 256, GSMEM>>>(
        xsh, xsl, 1280, nullptr, nullptr, 0, 1280,
        Wsh, Wsl, 1280, 512, 1280,
        b_s, nullptr, nullptr, 0, g_s, be_s,
        sfeats, 512, sfh, sfl, 512);
    // sgpre = sfeats @ Wih_s^T + bih_s + bhh_s
    gemm3_kernel<<<dim3(2048 / 128, MBT / 128), 256, GSMEM>>>(
        sfh, sfl, 512, nullptr, nullptr, 0, 512,
        Wish, Wisl, 512, 2048, 512,
        bih_s, bhh_s, nullptr, 0, nullptr, nullptr,
        sgpre, 2048, nullptr, nullptr, 0);
    // lgpre = [feats, sfeats] @ Wih_l^T + bih_l + bhh_l   (K-concat 2048+512)
    gemm3_kernel<<<dim3(4096 / 128, MBT / 128), 256, GSMEM>>>(
        fh, fl, 2048, sfh, sfl, 512, 2048,
        Wlh, Wll, 2560, 4096, 2560,
        bih_l, bhh_l, nullptr, 0, nullptr, nullptr,
        lgpre, 4096, nullptr, nullptr, 0);

    // ---- Phase 2: recurrence (2 launches per step)
    for (int t = 0; t < TT; t++) {
        int cur = t & 1, nxt = 1 - cur;
        float* hl_c = hl + (size_t)cur * BB * LL;
        float* cl_c = cl + (size_t)cur * BB * LL;
        float* hl_n = hl + (size_t)nxt * BB * LL;
        float* cl_n = cl + (size_t)nxt * BB * LL;
        float* cs_c = cs + (size_t)cur * BB * SS;
        float* hs_n = hs + (size_t)nxt * BB * SS;
        float* cs_n = cs + (size_t)nxt * BB * SS;
        bf16* hlh_c = hlh + (size_t)cur * BB * LL;
        bf16* hll_c = hll + (size_t)cur * BB * LL;
        bf16* hlh_n = hlh + (size_t)nxt * BB * LL;
        bf16* hll_n = hll + (size_t)nxt * BB * LL;
        bf16* hsh_c = hsh + (size_t)cur * BB * SS;
        bf16* hsl_c = hsl + (size_t)cur * BB * SS;
        bf16* hsh_n = hsh + (size_t)nxt * BB * SS;
        bf16* hsl_n = hsl + (size_t)nxt * BB * SS;
        float* r_t = out_r + (size_t)t * BB * 2;

        step_gemm_kernel<<<dim3(4096 / 128, BB / 128, 3), 256, GSMEM>>>(
            hsh_c, hsl_c, Whsh, Whsl, sgpre + (size_t)t * 2048,
            hlh_c, hll_c, Whlh, Whll, lgpre + (size_t)t * 4096,
            Gs, GlA, GlB);
        step_post_kernel<<<BB, 256>>>(
            Gs, GlA, GlB, sfeats, t, hl_c, cl_c, cs_c,
            hs_n, cs_n, hsh_n, hsl_n,
            W_g, b_g, r_t, hl_n, cl_n, hlh_n, hll_n);
    }

    // ---- classifier on final h_l (buffer 0 after 64 steps)
    gemm3_kernel<<<dim3((NCLS + 127) / 128, BB / 128), 256, GSMEM>>>(
        hlh, hll, 1024, nullptr, nullptr, 0, 1024,
        Wch, Wcl, 1024, NCLS, 1024,
        b_c, nullptr, nullptr, 0, nullptr, nullptr,
        out_logits, NCLS, nullptr, nullptr, 0);
}

// round 7
// speedup vs baseline: 2.1772x; 1.0369x over previous
#include <cuda_runtime.h>
#include <cuda_bf16.h>
#include <math.h>
#include <stdint.h>

// ---------------------------------------------------------------------------
// Problem constants
// ---------------------------------------------------------------------------
#define BB 256
#define TT 64
#define LL 1024
#define SS 512
#define NCLS 239
#define MBT (BB * TT)          // 16384

typedef __nv_bfloat16 bf16;

// ---------------------------------------------------------------------------
// Scratch (device globals; no runtime allocation allowed)
// ---------------------------------------------------------------------------
__device__ bf16 g_x_hi  [MBT * 2048];
__device__ bf16 g_x_lo  [MBT * 2048];
__device__ bf16 g_xs_hi [MBT * 1280];
__device__ bf16 g_xs_lo [MBT * 1280];
__device__ bf16 g_f_hi  [MBT * 2048];
__device__ bf16 g_f_lo  [MBT * 2048];
__device__ bf16 g_sf_hi [MBT * 512];
__device__ bf16 g_sf_lo [MBT * 512];
__device__ bf16 g_Wp_hi [2048 * 2048];
__device__ bf16 g_Wp_lo [2048 * 2048];
__device__ bf16 g_Ws_hi [512 * 1280];
__device__ bf16 g_Ws_lo [512 * 1280];
__device__ bf16 g_Wl_hi [4096 * 2560];   // Wih_l full (K-concat GEMM)
__device__ bf16 g_Wl_lo [4096 * 2560];
__device__ bf16 g_Whl_hi[4096 * 1024];   // Whh_l
__device__ bf16 g_Whl_lo[4096 * 1024];
__device__ bf16 g_Wis_hi[2048 * 512];    // Wih_s
__device__ bf16 g_Wis_lo[2048 * 512];
__device__ bf16 g_Whs_hi[2048 * 512];    // Whh_s
__device__ bf16 g_Whs_lo[2048 * 512];
__device__ bf16 g_Wc_hi [NCLS * 1024];
__device__ bf16 g_Wc_lo [NCLS * 1024];
__device__ float g_sfeats[MBT * 512];
__device__ float g_sgpre [MBT * 2048];
__device__ float g_lgpre [MBT * 4096];
__device__ float g_Gs [BB * 2048];
__device__ float g_GlA[BB * 4096];       // Gl K-half 0 (+ lgpre addsrc)
__device__ float g_GlB[BB * 4096];       // Gl K-half 1
__device__ float g_hl[2][BB * LL];
__device__ float g_cl[2][BB * LL];
__device__ float g_hs[2][BB * SS];
__device__ float g_cs[2][BB * SS];
__device__ bf16 g_hl_hi[2][BB * LL];
__device__ bf16 g_hl_lo[2][BB * LL];
__device__ bf16 g_hs_hi[2][BB * SS];
__device__ bf16 g_hs_lo[2][BB * SS];

// ---------------------------------------------------------------------------
// PTX helpers (legacy tensor path only — harness targets compute_100)
// ---------------------------------------------------------------------------
__device__ __forceinline__ uint32_t smem_u32(const void* p) {
    return (uint32_t)__cvta_generic_to_shared(p);
}
__device__ __forceinline__ void cp16(uint32_t dst, const void* src, int srcsize) {
    asm volatile("cp.async.cg.shared.global [%0], [%1], 16, %2;\n"
                 :: "r"(dst), "l"(src), "r"(srcsize));
}
__device__ __forceinline__ void cp_commit() {
    asm volatile("cp.async.commit_group;\n");
}
template<int N>
__device__ __forceinline__ void cp_wait() {
    asm volatile("cp.async.wait_group %0;\n" :: "n"(N));
}
__device__ __forceinline__ void ldsm4(uint32_t* r, uint32_t addr) {
    asm volatile("ldmatrix.sync.aligned.m8n8.x4.shared.b16 {%0,%1,%2,%3}, [%4];\n"
                 : "=r"(r[0]), "=r"(r[1]), "=r"(r[2]), "=r"(r[3]) : "r"(addr));
}
__device__ __forceinline__ void mma_bf16(float* d, const uint32_t* a, uint32_t b0, uint32_t b1) {
    asm volatile("mma.sync.aligned.m16n8k16.row.col.f32.bf16.bf16.f32 "
                 "{%0,%1,%2,%3},{%4,%5,%6,%7},{%8,%9},{%0,%1,%2,%3};\n"
                 : "+f"(d[0]), "+f"(d[1]), "+f"(d[2]), "+f"(d[3])
                 : "r"(a[0]), "r"(a[1]), "r"(a[2]), "r"(a[3]), "r"(b0), "r"(b1));
}

// ---------------------------------------------------------------------------
// Split-bf16 triple-product GEMM core (4-stage cp.async pipeline, 512 threads).
//   C[M,N] = epi( A@W^T ), A = A_hi+A_lo, W = W_hi+W_lo, computed as
//   Ahi*Whi + Ahi*Wlo + Alo*Whi. A may be a K-concat: cols [0,K1) from A,
//   [K1,K) from A2 (K1 % 32 == 0). BM=BN=128, 16 warps of 32x32 tiles
//   (32 accumulator regs/thread -> 2 CTAs/SM at 50% occupancy).
// ---------------------------------------------------------------------------
#define LDSH 40                       // halves per smem row (padded)
#define GSMEM (8 * 128 * LDSH * 2)    // 4 stages * (A + B) = 81920 bytes

__device__ __forceinline__ void gemm_core(
    char* smem, int bx, int by,
    const bf16* __restrict__ Ahi, const bf16* __restrict__ Alo, int lda,
    const bf16* __restrict__ A2hi, const bf16* __restrict__ A2lo, int lda2, int K1,
    const bf16* __restrict__ Bhi, const bf16* __restrict__ Blo, int ldb,
    int N, int K,
    const float* __restrict__ b1, const float* __restrict__ b2,
    const float* __restrict__ addsrc, int ldadd,
    const float* __restrict__ gamma, const float* __restrict__ beta,
    float* __restrict__ Cf, int ldc,
    bf16* __restrict__ Chi, bf16* __restrict__ Clo, int ldsp)
{
    constexpr int BM = 128, BN = 128;
    const int tid  = threadIdx.x;
    const int lane = tid & 31;
    const int wid  = tid >> 5;          // 0..15
    const int wm   = wid >> 2;          // 4 warp rows (32 each)
    const int wn   = wid & 3;           // 4 warp cols (32 each)
    const int bm   = by * BM;
    const int bn   = bx * BN;

    const int NK = K / 32;
    const int NS = 3 * NK;

    float acc[2][4][4];
#pragma unroll
    for (int i = 0; i < 2; i++)
#pragma unroll
        for (int j = 0; j < 4; j++)
#pragma unroll
            for (int r = 0; r < 4; r++) acc[i][j][r] = 0.f;

    // one cp16 per thread per tile (512 threads cover 128x32 halves)
    const int srow = tid >> 2;
    const int skc  = (tid & 3) * 8;
    auto stage = [&](int s) {
        int p  = s / NK;
        int k0 = (s - p * NK) * 32;
        const bf16* Ap; int ald, ak;
        if (k0 < K1) { Ap = (p == 2) ? Alo  : Ahi;  ald = lda;  ak = k0; }
        else         { Ap = (p == 2) ? A2lo : A2hi; ald = lda2; ak = k0 - K1; }
        const bf16* Bp = (p == 1) ? Blo : Bhi;
        uint32_t ab = smem_u32(smem) + (s & 3) * (BM * LDSH * 2);
        uint32_t bb = smem_u32(smem) + (4 + (s & 3)) * (BM * LDSH * 2);
        cp16(ab + (srow * LDSH + skc) * 2,
             Ap + (size_t)(bm + srow) * ald + ak + skc, 16);
        int n = bn + srow;
        bool ok = (n < N);
        cp16(bb + (srow * LDSH + skc) * 2,
             Bp + (size_t)(ok ? n : 0) * ldb + k0 + skc, ok ? 16 : 0);
    };

    stage(0); cp_commit();
    if (NS > 1) stage(1);
    cp_commit();
    if (NS > 2) stage(2);
    cp_commit();

    for (int s = 0; s < NS; s++) {
        cp_wait<2>();
        __syncthreads();   // stage s data landed; prior reads of buffer (s+3)&3 done
        if (s + 3 < NS) stage(s + 3);
        cp_commit();

        uint32_t asb = smem_u32(smem) + (s & 3) * (BM * LDSH * 2);
        uint32_t bsb = smem_u32(smem) + (4 + (s & 3)) * (BM * LDSH * 2);
#pragma unroll
        for (int ks = 0; ks < 32; ks += 16) {
            uint32_t a[2][4], b[4][2];
#pragma unroll
            for (int mi = 0; mi < 2; mi++) {
                int row = wm * 32 + mi * 16 + (lane & 15);
                int kk  = ks + (lane >> 4) * 8;
                ldsm4(a[mi], asb + (row * LDSH + kk) * 2);
            }
#pragma unroll
            for (int ng = 0; ng < 2; ng++) {
                int row = wn * 32 + ng * 16 + (lane & 7) + ((lane >> 4) << 3);
                int kk  = ks + (((lane >> 3) & 1) << 3);
                uint32_t t[4];
                ldsm4(t, bsb + (row * LDSH + kk) * 2);
                b[2 * ng][0] = t[0]; b[2 * ng][1] = t[1];
                b[2 * ng + 1][0] = t[2]; b[2 * ng + 1][1] = t[3];
            }
#pragma unroll
            for (int mi = 0; mi < 2; mi++)
#pragma unroll
                for (int nj = 0; nj < 4; nj++)
                    mma_bf16(acc[mi][nj], a[mi], b[nj][0], b[nj][1]);
        }
    }

    // ---- epilogue (register-resident)
    const float inv_std = rsqrtf(1.0f + 1e-5f);
    const int g  = lane >> 2;
    const int tg = lane & 3;
#pragma unroll
    for (int mi = 0; mi < 2; mi++)
#pragma unroll
        for (int nj = 0; nj < 4; nj++)
#pragma unroll
            for (int r = 0; r < 4; r++) {
                int m = bm + wm * 32 + mi * 16 + g + ((r >> 1) << 3);
                int n = bn + wn * 32 + nj * 8 + tg * 2 + (r & 1);
                if (n >= N) continue;
                float v = acc[mi][nj][r];
                if (b1)     v += b1[n];
                if (b2)     v += b2[n];
                if (addsrc) v += addsrc[(size_t)m * ldadd + n];
                if (gamma)  v = fmaxf(0.f, v * (gamma[n] * inv_std) + beta[n]);
                if (Cf)     Cf[(size_t)m * ldc + n] = v;
                if (Chi) {
                    bf16 h = __float2bfloat16(v);
                    Chi[(size_t)m * ldsp + n] = h;
                    Clo[(size_t)m * ldsp + n] = __float2bfloat16(v - __bfloat162float(h));
                }
            }
}

// standalone GEMM launcher (512 threads, 2 CTAs/SM)
__global__ void __launch_bounds__(512, 2)
gemm3_kernel(const bf16* Ahi, const bf16* Alo, int lda,
             const bf16* A2hi, const bf16* A2lo, int lda2, int K1,
             const bf16* Bhi, const bf16* Blo, int ldb,
             int N, int K,
             const float* b1, const float* b2,
             const float* addsrc, int ldadd,
             const float* gamma, const float* beta,
             float* Cf, int ldc,
             bf16* Chi, bf16* Clo, int ldsp)
{
    extern __shared__ char smem[];
    gemm_core(smem, blockIdx.x, blockIdx.y,
              Ahi, Alo, lda, A2hi, A2lo, lda2, K1, Bhi, Blo, ldb, N, K,
              b1, b2, addsrc, ldadd, gamma, beta, Cf, ldc, Chi, Clo, ldsp);
}

// fused per-step GEMM with split-K on Gl:
//   z==0 -> Gs   (N=2048, K=512, addsrc=sgpre_t)     [x < 16]
//   z==1 -> GlA  (N=4096, K=[0,512),  addsrc=lgpre_t)
//   z==2 -> GlB  (N=4096, K=[512,1024), no addsrc)
__global__ void __launch_bounds__(512, 2)
step_gemm_kernel(const bf16* hsh, const bf16* hsl, const bf16* Whsh, const bf16* Whsl,
                 const float* sgpre_t,
                 const bf16* hlh, const bf16* hll, const bf16* Whlh, const bf16* Whll,
                 const float* lgpre_t,
                 float* Gs, float* GlA, float* GlB)
{
    extern __shared__ char smem[];
    if (blockIdx.z == 0) {
        if (blockIdx.x >= 2048 / 128) return;
        gemm_core(smem, blockIdx.x, blockIdx.y,
                  hsh, hsl, 512, nullptr, nullptr, 0, 512,
                  Whsh, Whsl, 512, 2048, 512,
                  nullptr, nullptr, sgpre_t, TT * 2048, nullptr, nullptr,
                  Gs, 2048, nullptr, nullptr, 0);
    } else if (blockIdx.z == 1) {
        gemm_core(smem, blockIdx.x, blockIdx.y,
                  hlh, hll, 1024, nullptr, nullptr, 0, 1024,
                  Whlh, Whll, 1024, 4096, 512,
                  nullptr, nullptr, lgpre_t, TT * 4096, nullptr, nullptr,
                  GlA, 4096, nullptr, nullptr, 0);
    } else {
        gemm_core(smem, blockIdx.x, blockIdx.y,
                  hlh + 512, hll + 512, 1024, nullptr, nullptr, 0, 1024,
                  Whlh + 512, Whll + 512, 1024, 4096, 512,
                  nullptr, nullptr, nullptr, 0, nullptr, nullptr,
                  GlB, 4096, nullptr, nullptr, 0);
    }
}

// ---------------------------------------------------------------------------
// Elementwise kernels
// ---------------------------------------------------------------------------
__device__ __forceinline__ float sigf(float x) { return 1.f / (1.f + expf(-x)); }
__device__ __forceinline__ void split1(float v, bf16* hi, bf16* lo, size_t i) {
    bf16 h = __float2bfloat16(v);
    hi[i] = h;
    lo[i] = __float2bfloat16(v - __bfloat162float(h));
}

// one fused split kernel over all 9 tensors (float4-vectorized, grid-stride)
struct SJob { const float4* src; __nv_bfloat162* hi; __nv_bfloat162* lo; };
struct SJobs { SJob j[9]; unsigned cum[10]; };

__global__ void __launch_bounds__(256)
split_all_kernel(SJobs jb, unsigned total4)
{
    const unsigned stride = gridDim.x * blockDim.x;
    for (unsigned i = blockIdx.x * blockDim.x + threadIdx.x; i < total4; i += stride) {
        int k = 0;
#pragma unroll
        for (int q = 0; q < 8; q++) if (i >= jb.cum[q + 1]) k = q + 1;
        unsigned off = i - jb.cum[k];
        float4 v = jb.j[k].src[off];
        bf16 h0 = __float2bfloat16(v.x), h1 = __float2bfloat16(v.y);
        bf16 h2 = __float2bfloat16(v.z), h3 = __float2bfloat16(v.w);
        bf16 l0 = __float2bfloat16(v.x - __bfloat162float(h0));
        bf16 l1 = __float2bfloat16(v.y - __bfloat162float(h1));
        bf16 l2 = __float2bfloat16(v.z - __bfloat162float(h2));
        bf16 l3 = __float2bfloat16(v.w - __bfloat162float(h3));
        jb.j[k].hi[2 * off]     = __nv_bfloat162(h0, h1);
        jb.j[k].hi[2 * off + 1] = __nv_bfloat162(h2, h3);
        jb.j[k].lo[2 * off]     = __nv_bfloat162(l0, l1);
        jb.j[k].lo[2 * off + 1] = __nv_bfloat162(l2, l3);
    }
}

__global__ void zero_states_kernel(float* hl, float* cl, float* hs, float* cs,
                                   bf16* hlh, bf16* hll, bf16* hsh, bf16* hsl)
{
    int i = blockIdx.x * blockDim.x + threadIdx.x;
    if (i < BB * LL) { hl[i] = 0.f; cl[i] = 0.f; hlh[i] = __float2bfloat16(0.f); hll[i] = __float2bfloat16(0.f); }
    if (i < BB * SS) { hs[i] = 0.f; cs[i] = 0.f; hsh[i] = __float2bfloat16(0.f); hsl[i] = __float2bfloat16(0.f); }
}

// fused per-step post-GEMM kernel: small LSTM act + hard gate + large act/merge.
// One block per batch row. Gl = GlA + GlB (split-K halves).
__global__ void __launch_bounds__(256)
step_post_kernel(const float* __restrict__ Gs,
                 const float* __restrict__ GlA, const float* __restrict__ GlB,
                 const float* __restrict__ sfeats, int t,
                 const float* __restrict__ h_old, const float* __restrict__ c_old,
                 const float* __restrict__ cs_old,
                 float* __restrict__ hs_new, float* __restrict__ cs_new,
                 bf16* __restrict__ hsh, bf16* __restrict__ hsl,
                 const float* __restrict__ W_g, const float* __restrict__ b_g,
                 float* __restrict__ r_out,
                 float* __restrict__ h_new, float* __restrict__ c_new,
                 bf16* __restrict__ hh, bf16* __restrict__ hl)
{
    const int b   = blockIdx.x;
    const int tid = threadIdx.x;
    __shared__ float sh_h[SS], sh_c[SS];
    __shared__ float s0[256], s1[256];
    __shared__ float r0sh;

    // ---- small LSTM activation (writes smem + global)
    const float* gs = Gs + (size_t)b * (4 * SS);
    for (int n = tid; n < SS; n += 256) {
        float i_ = sigf(gs[n]);
        float f_ = sigf(gs[SS + n]);
        float gg = tanhf(gs[2 * SS + n]);
        float o_ = sigf(gs[3 * SS + n]);
        float c2 = f_ * cs_old[(size_t)b * SS + n] + i_ * gg;
        float h2 = o_ * tanhf(c2);
        sh_h[n] = h2; sh_c[n] = c2;
        cs_new[(size_t)b * SS + n] = c2;
        hs_new[(size_t)b * SS + n] = h2;
        split1(h2, hsh, hsl, (size_t)b * SS + n);
    }

    // ---- hard gate on OLD large state: r = one_hot(argmax(p))
    const float* s = sfeats + ((size_t)b * TT + t) * SS;
    const float* h = h_old + (size_t)b * LL;
    const float* c = c_old + (size_t)b * LL;
    const float* w0 = W_g;
    const float* w1 = W_g + 2560;
    float p0 = 0.f, p1 = 0.f;
    for (int j = tid; j < SS; j += 256) { float v = s[j]; p0 += v * w0[j]; p1 += v * w1[j]; }
    for (int j = tid; j < LL; j += 256) { float v = h[j]; p0 += v * w0[SS + j]; p1 += v * w1[SS + j]; }
    for (int j = tid; j < LL; j += 256) { float v = c[j]; p0 += v * w0[SS + LL + j]; p1 += v * w1[SS + LL + j]; }
    s0[tid] = p0; s1[tid] = p1;
    __syncthreads();                       // also publishes sh_h/sh_c
    for (int st = 128; st > 0; st >>= 1) {
        if (tid < st) { s0[tid] += s0[tid + st]; s1[tid] += s1[tid + st]; }
        __syncthreads();
    }
    if (tid == 0) {
        float r0 = (s0[0] + b_g[0] >= s1[0] + b_g[1]) ? 1.f : 0.f;
        r0sh = r0;
        r_out[b * 2 + 0] = r0;
        r_out[b * 2 + 1] = 1.f - r0;
    }
    __syncthreads();
    const float r0 = r0sh, r1 = 1.f - r0sh;

    // ---- large LSTM activation + straight-through merge
    const float* gA = GlA + (size_t)b * (4 * LL);
    const float* gB = GlB + (size_t)b * (4 * LL);
    for (int n = tid; n < LL; n += 256) {
        size_t idx = (size_t)b * LL + n;
        float i_ = sigf(gA[n] + gB[n]);
        float f_ = sigf(gA[LL + n] + gB[LL + n]);
        float gg = tanhf(gA[2 * LL + n] + gB[2 * LL + n]);
        float o_ = sigf(gA[3 * LL + n] + gB[3 * LL + n]);
        float c_ln = f_ * c_old[idx] + i_ * gg;
        float h_ln = o_ * tanhf(c_ln);
        float ph = (n < SS) ? sh_h[n] : h_old[idx];
        float pc = (n < SS) ? sh_c[n] : c_old[idx];
        float h2 = r0 * h_ln + r1 * ph;
        c_new[idx] = r0 * c_ln + r1 * pc;
        h_new[idx] = h2;
        split1(h2, hh, hl, idx);
    }
}

// ---------------------------------------------------------------------------
// Launch
// ---------------------------------------------------------------------------
static inline float* fsym(const void* s) { void* p = nullptr; cudaGetSymbolAddress(&p, s); return (float*)p; }
static inline bf16*  bsym(const void* s) { void* p = nullptr; cudaGetSymbolAddress(&p, s); return (bf16*)p; }

extern "C" void kernel_launch(void* const* d_in, const int* in_sizes, int n_in,
                              void* d_out, int out_size)
{
    const float* x     = (const float*)d_in[0];
    const float* xs    = (const float*)d_in[1];
    const float* W_p   = (const float*)d_in[2];
    const float* b_p   = (const float*)d_in[3];
    const float* g_p   = (const float*)d_in[4];
    const float* be_p  = (const float*)d_in[5];
    const float* W_s   = (const float*)d_in[6];
    const float* b_s   = (const float*)d_in[7];
    const float* g_s   = (const float*)d_in[8];
    const float* be_s  = (const float*)d_in[9];
    const float* Wih_l = (const float*)d_in[10];
    const float* Whh_l = (const float*)d_in[11];
    const float* bih_l = (const float*)d_in[12];
    const float* bhh_l = (const float*)d_in[13];
    const float* Wih_s = (const float*)d_in[14];
    const float* Whh_s = (const float*)d_in[15];
    const float* bih_s = (const float*)d_in[16];
    const float* bhh_s = (const float*)d_in[17];
    const float* W_g   = (const float*)d_in[18];
    const float* b_g   = (const float*)d_in[19];
    const float* W_c   = (const float*)d_in[20];
    const float* b_c   = (const float*)d_in[21];

    float* out = (float*)d_out;
    float* out_logits = out;
    float* out_r      = out + BB * NCLS;

    bf16 *xh = bsym(g_x_hi), *xl = bsym(g_x_lo);
    bf16 *xsh = bsym(g_xs_hi), *xsl = bsym(g_xs_lo);
    bf16 *fh = bsym(g_f_hi), *fl = bsym(g_f_lo);
    bf16 *sfh = bsym(g_sf_hi), *sfl = bsym(g_sf_lo);
    bf16 *Wph = bsym(g_Wp_hi), *Wpl = bsym(g_Wp_lo);
    bf16 *Wsh = bsym(g_Ws_hi), *Wsl = bsym(g_Ws_lo);
    bf16 *Wlh = bsym(g_Wl_hi), *Wll = bsym(g_Wl_lo);
    bf16 *Whlh = bsym(g_Whl_hi), *Whll = bsym(g_Whl_lo);
    bf16 *Wish = bsym(g_Wis_hi), *Wisl = bsym(g_Wis_lo);
    bf16 *Whsh = bsym(g_Whs_hi), *Whsl = bsym(g_Whs_lo);
    bf16 *Wch = bsym(g_Wc_hi), *Wcl = bsym(g_Wc_lo);

    float* sfeats = fsym(g_sfeats);
    float* sgpre  = fsym(g_sgpre);
    float* lgpre  = fsym(g_lgpre);
    float* Gs  = fsym(g_Gs);
    float* GlA = fsym(g_GlA);
    float* GlB = fsym(g_GlB);
    float* hl = fsym(g_hl);
    float* cl = fsym(g_cl);
    float* hs = fsym(g_hs);
    float* cs = fsym(g_cs);
    bf16* hlh = bsym(g_hl_hi); bf16* hll = bsym(g_hl_lo);
    bf16* hsh = bsym(g_hs_hi); bf16* hsl = bsym(g_hs_lo);

    cudaFuncSetAttribute(gemm3_kernel, cudaFuncAttributeMaxDynamicSharedMemorySize, GSMEM);
    cudaFuncSetAttribute(step_gemm_kernel, cudaFuncAttributeMaxDynamicSharedMemorySize, GSMEM);

    const int TPB = 256;

    // ---- fused split of all inputs & weights into bf16 pairs
    {
        SJobs jb;
        const float* srcs[9] = { x, xs, W_p, W_s, Wih_l, Whh_l, Wih_s, Whh_s, W_c };
        bf16* his[9] = { xh, xsh, Wph, Wsh, Wlh, Whlh, Wish, Whsh, Wch };
        bf16* los[9] = { xl, xsl, Wpl, Wsl, Wll, Whll, Wisl, Whsl, Wcl };
        long  ns [9] = { (long)MBT * 2048, (long)MBT * 1280, 2048L * 2048, 512L * 1280,
                         4096L * 2560, 4096L * 1024, 2048L * 512, 2048L * 512,
                         (long)NCLS * 1024 };
        unsigned cum = 0;
        for (int k = 0; k < 9; k++) {
            jb.j[k].src = (const float4*)srcs[k];
            jb.j[k].hi  = (__nv_bfloat162*)his[k];
            jb.j[k].lo  = (__nv_bfloat162*)los[k];
            jb.cum[k] = cum;
            cum += (unsigned)(ns[k] / 4);
        }
        jb.cum[9] = cum;
        int grid = (int)((cum / 2 + TPB - 1) / TPB);     // 2 float4 per thread
        split_all_kernel<<<grid, TPB>>>(jb, cum);
    }
    zero_states_kernel<<<(BB * LL + 255) / 256, TPB>>>(hl, cl, hs, cs, hlh, hll, hsh, hsl);

    // ---- Phase 1: time-parallel GEMMs
    // feats(split) = relu(BN(x @ W_p^T + b_p))
    gemm3_kernel<<<dim3(2048 / 128, MBT / 128), 512, GSMEM>>>(
        xh, xl, 2048, nullptr, nullptr, 0, 2048,
        Wph, Wpl, 2048, 2048, 2048,
        b_p, nullptr, nullptr, 0, g_p, be_p,
        nullptr, 0, fh, fl, 2048);
    // sfeats(fp32+split) = relu(BN(xs @ W_s^T + b_s))
    gemm3_kernel<<<dim3(512 / 128, MBT / 128), 512, GSMEM>>>(
        xsh, xsl, 1280, nullptr, nullptr, 0, 1280,
        Wsh, Wsl, 1280, 512, 1280,
        b_s, nullptr, nullptr, 0, g_s, be_s,
        sfeats, 512, sfh, sfl, 512);
    // sgpre = sfeats @ Wih_s^T + bih_s + bhh_s
    gemm3_kernel<<<dim3(2048 / 128, MBT / 128), 512, GSMEM>>>(
        sfh, sfl, 512, nullptr, nullptr, 0, 512,
        Wish, Wisl, 512, 2048, 512,
        bih_s, bhh_s, nullptr, 0, nullptr, nullptr,
        sgpre, 2048, nullptr, nullptr, 0);
    // lgpre = [feats, sfeats] @ Wih_l^T + bih_l + bhh_l   (K-concat 2048+512)
    gemm3_kernel<<<dim3(4096 / 128, MBT / 128), 512, GSMEM>>>(
        fh, fl, 2048, sfh, sfl, 512, 2048,
        Wlh, Wll, 2560, 4096, 2560,
        bih_l, bhh_l, nullptr, 0, nullptr, nullptr,
        lgpre, 4096, nullptr, nullptr, 0);

    // ---- Phase 2: recurrence (2 launches per step)
    for (int t = 0; t < TT; t++) {
        int cur = t & 1, nxt = 1 - cur;
        float* hl_c = hl + (size_t)cur * BB * LL;
        float* cl_c = cl + (size_t)cur * BB * LL;
        float* hl_n = hl + (size_t)nxt * BB * LL;
        float* cl_n = cl + (size_t)nxt * BB * LL;
        float* cs_c = cs + (size_t)cur * BB * SS;
        float* hs_n = hs + (size_t)nxt * BB * SS;
        float* cs_n = cs + (size_t)nxt * BB * SS;
        bf16* hlh_c = hlh + (size_t)cur * BB * LL;
        bf16* hll_c = hll + (size_t)cur * BB * LL;
        bf16* hlh_n = hlh + (size_t)nxt * BB * LL;
        bf16* hll_n = hll + (size_t)nxt * BB * LL;
        bf16* hsh_c = hsh + (size_t)cur * BB * SS;
        bf16* hsl_c = hsl + (size_t)cur * BB * SS;
        bf16* hsh_n = hsh + (size_t)nxt * BB * SS;
        bf16* hsl_n = hsl + (size_t)nxt * BB * SS;
        float* r_t = out_r + (size_t)t * BB * 2;

        step_gemm_kernel<<<dim3(4096 / 128, BB / 128, 3), 512, GSMEM>>>(
            hsh_c, hsl_c, Whsh, Whsl, sgpre + (size_t)t * 2048,
            hlh_c, hll_c, Whlh, Whll, lgpre + (size_t)t * 4096,
            Gs, GlA, GlB);
        step_post_kernel<<<BB, 256>>>(
            Gs, GlA, GlB, sfeats, t, hl_c, cl_c, cs_c,
            hs_n, cs_n, hsh_n, hsl_n,
            W_g, b_g, r_t, hl_n, cl_n, hlh_n, hll_n);
    }

    // ---- classifier on final h_l (buffer 0 after 64 steps)
    gemm3_kernel<<<dim3((NCLS + 127) / 128, BB / 128), 512, GSMEM>>>(
        hlh, hll, 1024, nullptr, nullptr, 0, 1024,
        Wch, Wcl, 1024, NCLS, 1024,
        b_c, nullptr, nullptr, 0, nullptr, nullptr,
        out_logits, NCLS, nullptr, nullptr, 0);
}

// round 8
// speedup vs baseline: 2.3010x; 1.0569x over previous
#include <cuda_runtime.h>
#include <cuda_bf16.h>
#include <math.h>
#include <stdint.h>

// ---------------------------------------------------------------------------
// Problem constants
// ---------------------------------------------------------------------------
#define BB 256
#define TT 64
#define LL 1024
#define SS 512
#define NCLS 239
#define MBT (BB * TT)          // 16384

typedef __nv_bfloat16 bf16;

// ---------------------------------------------------------------------------
// Scratch (device globals; no runtime allocation allowed)
// ---------------------------------------------------------------------------
__device__ bf16 g_x_hi  [MBT * 2048];
__device__ bf16 g_x_lo  [MBT * 2048];
__device__ bf16 g_xs_hi [MBT * 1280];
__device__ bf16 g_xs_lo [MBT * 1280];
__device__ bf16 g_f_hi  [MBT * 2048];
__device__ bf16 g_f_lo  [MBT * 2048];
__device__ bf16 g_sf_hi [MBT * 512];
__device__ bf16 g_sf_lo [MBT * 512];
__device__ bf16 g_Wp_hi [2048 * 2048];
__device__ bf16 g_Wp_lo [2048 * 2048];
__device__ bf16 g_Ws_hi [512 * 1280];
__device__ bf16 g_Ws_lo [512 * 1280];
__device__ bf16 g_Wl_hi [4096 * 2560];   // Wih_l full (K-concat GEMM)
__device__ bf16 g_Wl_lo [4096 * 2560];
__device__ bf16 g_Whl_hi[4096 * 1024];   // Whh_l
__device__ bf16 g_Whl_lo[4096 * 1024];
__device__ bf16 g_Wis_hi[2048 * 512];    // Wih_s
__device__ bf16 g_Wis_lo[2048 * 512];
__device__ bf16 g_Whs_hi[2048 * 512];    // Whh_s
__device__ bf16 g_Whs_lo[2048 * 512];
__device__ bf16 g_Wc_hi [NCLS * 1024];
__device__ bf16 g_Wc_lo [NCLS * 1024];
__device__ float g_sfeats[MBT * 512];
__device__ float g_sgpre [MBT * 2048];
__device__ float g_lgpre [MBT * 4096];
__device__ float g_Gs [BB * 2048];
__device__ float g_GlA[BB * 4096];       // Gl K-half 0 (+ lgpre addsrc)
__device__ float g_GlB[BB * 4096];       // Gl K-half 1
__device__ float g_hl[2][BB * LL];
__device__ float g_cl[2][BB * LL];
__device__ float g_hs[2][BB * SS];
__device__ float g_cs[2][BB * SS];
__device__ bf16 g_hl_hi[2][BB * LL];
__device__ bf16 g_hl_lo[2][BB * LL];
__device__ bf16 g_hs_hi[2][BB * SS];
__device__ bf16 g_hs_lo[2][BB * SS];

// ---------------------------------------------------------------------------
// PTX helpers (legacy tensor path only — harness targets compute_100)
// ---------------------------------------------------------------------------
__device__ __forceinline__ uint32_t smem_u32(const void* p) {
    return (uint32_t)__cvta_generic_to_shared(p);
}
__device__ __forceinline__ void cp16(uint32_t dst, const void* src, int srcsize) {
    asm volatile("cp.async.cg.shared.global [%0], [%1], 16, %2;\n"
                 :: "r"(dst), "l"(src), "r"(srcsize));
}
__device__ __forceinline__ void cp_commit() {
    asm volatile("cp.async.commit_group;\n");
}
template<int N>
__device__ __forceinline__ void cp_wait() {
    asm volatile("cp.async.wait_group %0;\n" :: "n"(N));
}
__device__ __forceinline__ void ldsm4(uint32_t* r, uint32_t addr) {
    asm volatile("ldmatrix.sync.aligned.m8n8.x4.shared.b16 {%0,%1,%2,%3}, [%4];\n"
                 : "=r"(r[0]), "=r"(r[1]), "=r"(r[2]), "=r"(r[3]) : "r"(addr));
}
__device__ __forceinline__ void mma_bf16(float* d, const uint32_t* a, uint32_t b0, uint32_t b1) {
    asm volatile("mma.sync.aligned.m16n8k16.row.col.f32.bf16.bf16.f32 "
                 "{%0,%1,%2,%3},{%4,%5,%6,%7},{%8,%9},{%0,%1,%2,%3};\n"
                 : "+f"(d[0]), "+f"(d[1]), "+f"(d[2]), "+f"(d[3])
                 : "r"(a[0]), "r"(a[1]), "r"(a[2]), "r"(a[3]), "r"(b0), "r"(b1));
}

// ---------------------------------------------------------------------------
// Split-bf16 triple-product GEMM core, register-reuse schedule.
//   C[M,N] = epi( A@W^T ), A = A_hi+A_lo, W = W_hi+W_lo, computed as
//   Ahi*Whi + Ahi*Wlo + Alo*Whi accumulated in fp32.
//   One pipeline stage = one K32 chunk holding ALL FOUR tiles
//   {Ahi, Alo, Bhi, Blo}; each warp ldsm's fragments once per k16 and issues
//   all 3 products from registers (8 ldsm4 : 24 HMMA).
//   BM=BN=128, 512 threads (16 warps, 32x32 tiles), 4-stage ring, 1 CTA/SM.
//   A may be a K-concat: cols [0,K1) from A, [K1,K) from A2 (K1 % 32 == 0).
// ---------------------------------------------------------------------------
#define LDSH 40                         // halves per smem row (padded)
#define TILEB (128 * LDSH * 2)          // one tile = 10240 bytes
#define NSTG 4
#define GSMEM (NSTG * 4 * TILEB)        // 163840 bytes

__device__ __forceinline__ void gemm_core(
    char* smem, int bx, int by,
    const bf16* __restrict__ Ahi, const bf16* __restrict__ Alo, int lda,
    const bf16* __restrict__ A2hi, const bf16* __restrict__ A2lo, int lda2, int K1,
    const bf16* __restrict__ Bhi, const bf16* __restrict__ Blo, int ldb,
    int N, int K,
    const float* __restrict__ b1, const float* __restrict__ b2,
    const float* __restrict__ addsrc, int ldadd,
    const float* __restrict__ gamma, const float* __restrict__ beta,
    float* __restrict__ Cf, int ldc,
    bf16* __restrict__ Chi, bf16* __restrict__ Clo, int ldsp)
{
    constexpr int BM = 128;
    const int tid  = threadIdx.x;
    const int lane = tid & 31;
    const int wid  = tid >> 5;          // 0..15
    const int wm   = wid >> 2;          // 4 warp rows (32 each)
    const int wn   = wid & 3;           // 4 warp cols (32 each)
    const int bm   = by * BM;
    const int bn   = bx * BM;

    const int NC = K / 32;              // K32 chunks

    float acc[2][4][4];
#pragma unroll
    for (int i = 0; i < 2; i++)
#pragma unroll
        for (int j = 0; j < 4; j++)
#pragma unroll
            for (int r = 0; r < 4; r++) acc[i][j][r] = 0.f;

    // one cp16 per thread per tile (512 threads cover a 128x32 tile)
    const int srow = tid >> 2;
    const int skc  = (tid & 3) * 8;
    auto stage = [&](int c) {
        int k0 = c * 32;
        const bf16 *Ah, *Al; int ald, ak;
        if (k0 < K1) { Ah = Ahi;  Al = Alo;  ald = lda;  ak = k0; }
        else         { Ah = A2hi; Al = A2lo; ald = lda2; ak = k0 - K1; }
        uint32_t base = smem_u32(smem) + (c & (NSTG - 1)) * (4 * TILEB);
        uint32_t soff = (srow * LDSH + skc) * 2;
        size_t aoff = (size_t)(bm + srow) * ald + ak + skc;
        cp16(base + 0 * TILEB + soff, Ah + aoff, 16);
        cp16(base + 1 * TILEB + soff, Al + aoff, 16);
        int n = bn + srow;
        bool ok = (n < N);
        size_t boff = (size_t)(ok ? n : 0) * ldb + k0 + skc;
        cp16(base + 2 * TILEB + soff, Bhi + boff, ok ? 16 : 0);
        cp16(base + 3 * TILEB + soff, Blo + boff, ok ? 16 : 0);
    };

    stage(0); cp_commit();
    if (NC > 1) stage(1);
    cp_commit();
    if (NC > 2) stage(2);
    cp_commit();

    // fragment addresses (fixed per thread, K-offset varies)
    const int arow = wm * 32 + (lane & 15);
    const int akk0 = (lane >> 4) * 8;
    const int brow = wn * 32 + (lane & 7) + ((lane >> 4) << 3);
    const int bkk0 = ((lane >> 3) & 1) << 3;

    for (int c = 0; c < NC; c++) {
        cp_wait<2>();
        __syncthreads();   // chunk c landed; all warps done reading chunk c-1
        if (c + 3 < NC) stage(c + 3);
        cp_commit();

        uint32_t base = smem_u32(smem) + (c & (NSTG - 1)) * (4 * TILEB);
#pragma unroll
        for (int ks = 0; ks < 32; ks += 16) {
            uint32_t ah[2][4], al[2][4], bh[4][2], bl[4][2];
            const int akk = ks + akk0;
            const int bkk = ks + bkk0;
#pragma unroll
            for (int mi = 0; mi < 2; mi++) {
                uint32_t ro = ((arow + mi * 16) * LDSH + akk) * 2;
                ldsm4(ah[mi], base + 0 * TILEB + ro);
                ldsm4(al[mi], base + 1 * TILEB + ro);
            }
#pragma unroll
            for (int ng = 0; ng < 2; ng++) {
                uint32_t ro = ((brow + ng * 16) * LDSH + bkk) * 2;
                uint32_t t[4];
                ldsm4(t, base + 2 * TILEB + ro);
                bh[2 * ng][0] = t[0]; bh[2 * ng][1] = t[1];
                bh[2 * ng + 1][0] = t[2]; bh[2 * ng + 1][1] = t[3];
                ldsm4(t, base + 3 * TILEB + ro);
                bl[2 * ng][0] = t[0]; bl[2 * ng][1] = t[1];
                bl[2 * ng + 1][0] = t[2]; bl[2 * ng + 1][1] = t[3];
            }
            // 3 products, full register reuse
#pragma unroll
            for (int mi = 0; mi < 2; mi++)
#pragma unroll
                for (int nj = 0; nj < 4; nj++)
                    mma_bf16(acc[mi][nj], ah[mi], bh[nj][0], bh[nj][1]);
#pragma unroll
            for (int mi = 0; mi < 2; mi++)
#pragma unroll
                for (int nj = 0; nj < 4; nj++)
                    mma_bf16(acc[mi][nj], ah[mi], bl[nj][0], bl[nj][1]);
#pragma unroll
            for (int mi = 0; mi < 2; mi++)
#pragma unroll
                for (int nj = 0; nj < 4; nj++)
                    mma_bf16(acc[mi][nj], al[mi], bh[nj][0], bh[nj][1]);
        }
    }

    // ---- epilogue (register-resident)
    const float inv_std = rsqrtf(1.0f + 1e-5f);
    const int g  = lane >> 2;
    const int tg = lane & 3;
#pragma unroll
    for (int mi = 0; mi < 2; mi++)
#pragma unroll
        for (int nj = 0; nj < 4; nj++)
#pragma unroll
            for (int r = 0; r < 4; r++) {
                int m = bm + wm * 32 + mi * 16 + g + ((r >> 1) << 3);
                int n = bn + wn * 32 + nj * 8 + tg * 2 + (r & 1);
                if (n >= N) continue;
                float v = acc[mi][nj][r];
                if (b1)     v += b1[n];
                if (b2)     v += b2[n];
                if (addsrc) v += addsrc[(size_t)m * ldadd + n];
                if (gamma)  v = fmaxf(0.f, v * (gamma[n] * inv_std) + beta[n]);
                if (Cf)     Cf[(size_t)m * ldc + n] = v;
                if (Chi) {
                    bf16 h = __float2bfloat16(v);
                    Chi[(size_t)m * ldsp + n] = h;
                    Clo[(size_t)m * ldsp + n] = __float2bfloat16(v - __bfloat162float(h));
                }
            }
}

// standalone GEMM launcher (512 threads, 1 CTA/SM)
__global__ void __launch_bounds__(512, 1)
gemm3_kernel(const bf16* Ahi, const bf16* Alo, int lda,
             const bf16* A2hi, const bf16* A2lo, int lda2, int K1,
             const bf16* Bhi, const bf16* Blo, int ldb,
             int N, int K,
             const float* b1, const float* b2,
             const float* addsrc, int ldadd,
             const float* gamma, const float* beta,
             float* Cf, int ldc,
             bf16* Chi, bf16* Clo, int ldsp)
{
    extern __shared__ char smem[];
    gemm_core(smem, blockIdx.x, blockIdx.y,
              Ahi, Alo, lda, A2hi, A2lo, lda2, K1, Bhi, Blo, ldb, N, K,
              b1, b2, addsrc, ldadd, gamma, beta, Cf, ldc, Chi, Clo, ldsp);
}

// fused per-step GEMM with split-K on Gl:
//   z==0 -> Gs   (N=2048, K=512, addsrc=sgpre_t)     [x < 16]
//   z==1 -> GlA  (N=4096, K=[0,512),  addsrc=lgpre_t)
//   z==2 -> GlB  (N=4096, K=[512,1024), no addsrc)
__global__ void __launch_bounds__(512, 1)
step_gemm_kernel(const bf16* hsh, const bf16* hsl, const bf16* Whsh, const bf16* Whsl,
                 const float* sgpre_t,
                 const bf16* hlh, const bf16* hll, const bf16* Whlh, const bf16* Whll,
                 const float* lgpre_t,
                 float* Gs, float* GlA, float* GlB)
{
    extern __shared__ char smem[];
    if (blockIdx.z == 0) {
        if (blockIdx.x >= 2048 / 128) return;
        gemm_core(smem, blockIdx.x, blockIdx.y,
                  hsh, hsl, 512, nullptr, nullptr, 0, 512,
                  Whsh, Whsl, 512, 2048, 512,
                  nullptr, nullptr, sgpre_t, TT * 2048, nullptr, nullptr,
                  Gs, 2048, nullptr, nullptr, 0);
    } else if (blockIdx.z == 1) {
        gemm_core(smem, blockIdx.x, blockIdx.y,
                  hlh, hll, 1024, nullptr, nullptr, 0, 1024,
                  Whlh, Whll, 1024, 4096, 512,
                  nullptr, nullptr, lgpre_t, TT * 4096, nullptr, nullptr,
                  GlA, 4096, nullptr, nullptr, 0);
    } else {
        gemm_core(smem, blockIdx.x, blockIdx.y,
                  hlh + 512, hll + 512, 1024, nullptr, nullptr, 0, 1024,
                  Whlh + 512, Whll + 512, 1024, 4096, 512,
                  nullptr, nullptr, nullptr, 0, nullptr, nullptr,
                  GlB, 4096, nullptr, nullptr, 0);
    }
}

// ---------------------------------------------------------------------------
// Elementwise kernels
// ---------------------------------------------------------------------------
__device__ __forceinline__ float sigf(float x) { return 1.f / (1.f + expf(-x)); }
__device__ __forceinline__ void split1(float v, bf16* hi, bf16* lo, size_t i) {
    bf16 h = __float2bfloat16(v);
    hi[i] = h;
    lo[i] = __float2bfloat16(v - __bfloat162float(h));
}

// one fused split kernel over all 9 tensors (float4-vectorized, grid-stride)
struct SJob { const float4* src; __nv_bfloat162* hi; __nv_bfloat162* lo; };
struct SJobs { SJob j[9]; unsigned cum[10]; };

__global__ void __launch_bounds__(256)
split_all_kernel(SJobs jb, unsigned total4)
{
    const unsigned stride = gridDim.x * blockDim.x;
    for (unsigned i = blockIdx.x * blockDim.x + threadIdx.x; i < total4; i += stride) {
        int k = 0;
#pragma unroll
        for (int q = 0; q < 8; q++) if (i >= jb.cum[q + 1]) k = q + 1;
        unsigned off = i - jb.cum[k];
        float4 v = jb.j[k].src[off];
        bf16 h0 = __float2bfloat16(v.x), h1 = __float2bfloat16(v.y);
        bf16 h2 = __float2bfloat16(v.z), h3 = __float2bfloat16(v.w);
        bf16 l0 = __float2bfloat16(v.x - __bfloat162float(h0));
        bf16 l1 = __float2bfloat16(v.y - __bfloat162float(h1));
        bf16 l2 = __float2bfloat16(v.z - __bfloat162float(h2));
        bf16 l3 = __float2bfloat16(v.w - __bfloat162float(h3));
        jb.j[k].hi[2 * off]     = __nv_bfloat162(h0, h1);
        jb.j[k].hi[2 * off + 1] = __nv_bfloat162(h2, h3);
        jb.j[k].lo[2 * off]     = __nv_bfloat162(l0, l1);
        jb.j[k].lo[2 * off + 1] = __nv_bfloat162(l2, l3);
    }
}

__global__ void zero_states_kernel(float* hl, float* cl, float* hs, float* cs,
                                   bf16* hlh, bf16* hll, bf16* hsh, bf16* hsl)
{
    int i = blockIdx.x * blockDim.x + threadIdx.x;
    if (i < BB * LL) { hl[i] = 0.f; cl[i] = 0.f; hlh[i] = __float2bfloat16(0.f); hll[i] = __float2bfloat16(0.f); }
    if (i < BB * SS) { hs[i] = 0.f; cs[i] = 0.f; hsh[i] = __float2bfloat16(0.f); hsl[i] = __float2bfloat16(0.f); }
}

// fused per-step post-GEMM kernel: small LSTM act + hard gate + large act/merge.
// One block per batch row. Gl = GlA + GlB (split-K halves).
__global__ void __launch_bounds__(256)
step_post_kernel(const float* __restrict__ Gs,
                 const float* __restrict__ GlA, const float* __restrict__ GlB,
                 const float* __restrict__ sfeats, int t,
                 const float* __restrict__ h_old, const float* __restrict__ c_old,
                 const float* __restrict__ cs_old,
                 float* __restrict__ hs_new, float* __restrict__ cs_new,
                 bf16* __restrict__ hsh, bf16* __restrict__ hsl,
                 const float* __restrict__ W_g, const float* __restrict__ b_g,
                 float* __restrict__ r_out,
                 float* __restrict__ h_new, float* __restrict__ c_new,
                 bf16* __restrict__ hh, bf16* __restrict__ hl)
{
    const int b   = blockIdx.x;
    const int tid = threadIdx.x;
    __shared__ float sh_h[SS], sh_c[SS];
    __shared__ float s0[256], s1[256];
    __shared__ float r0sh;

    // ---- small LSTM activation (writes smem + global)
    const float* gs = Gs + (size_t)b * (4 * SS);
    for (int n = tid; n < SS; n += 256) {
        float i_ = sigf(gs[n]);
        float f_ = sigf(gs[SS + n]);
        float gg = tanhf(gs[2 * SS + n]);
        float o_ = sigf(gs[3 * SS + n]);
        float c2 = f_ * cs_old[(size_t)b * SS + n] + i_ * gg;
        float h2 = o_ * tanhf(c2);
        sh_h[n] = h2; sh_c[n] = c2;
        cs_new[(size_t)b * SS + n] = c2;
        hs_new[(size_t)b * SS + n] = h2;
        split1(h2, hsh, hsl, (size_t)b * SS + n);
    }

    // ---- hard gate on OLD large state: r = one_hot(argmax(p))
    const float* s = sfeats + ((size_t)b * TT + t) * SS;
    const float* h = h_old + (size_t)b * LL;
    const float* c = c_old + (size_t)b * LL;
    const float* w0 = W_g;
    const float* w1 = W_g + 2560;
    float p0 = 0.f, p1 = 0.f;
    for (int j = tid; j < SS; j += 256) { float v = s[j]; p0 += v * w0[j]; p1 += v * w1[j]; }
    for (int j = tid; j < LL; j += 256) { float v = h[j]; p0 += v * w0[SS + j]; p1 += v * w1[SS + j]; }
    for (int j = tid; j < LL; j += 256) { float v = c[j]; p0 += v * w0[SS + LL + j]; p1 += v * w1[SS + LL + j]; }
    s0[tid] = p0; s1[tid] = p1;
    __syncthreads();                       // also publishes sh_h/sh_c
    for (int st = 128; st > 0; st >>= 1) {
        if (tid < st) { s0[tid] += s0[tid + st]; s1[tid] += s1[tid + st]; }
        __syncthreads();
    }
    if (tid == 0) {
        float r0 = (s0[0] + b_g[0] >= s1[0] + b_g[1]) ? 1.f : 0.f;
        r0sh = r0;
        r_out[b * 2 + 0] = r0;
        r_out[b * 2 + 1] = 1.f - r0;
    }
    __syncthreads();
    const float r0 = r0sh, r1 = 1.f - r0sh;

    // ---- large LSTM activation + straight-through merge
    const float* gA = GlA + (size_t)b * (4 * LL);
    const float* gB = GlB + (size_t)b * (4 * LL);
    for (int n = tid; n < LL; n += 256) {
        size_t idx = (size_t)b * LL + n;
        float i_ = sigf(gA[n] + gB[n]);
        float f_ = sigf(gA[LL + n] + gB[LL + n]);
        float gg = tanhf(gA[2 * LL + n] + gB[2 * LL + n]);
        float o_ = sigf(gA[3 * LL + n] + gB[3 * LL + n]);
        float c_ln = f_ * c_old[idx] + i_ * gg;
        float h_ln = o_ * tanhf(c_ln);
        float ph = (n < SS) ? sh_h[n] : h_old[idx];
        float pc = (n < SS) ? sh_c[n] : c_old[idx];
        float h2 = r0 * h_ln + r1 * ph;
        c_new[idx] = r0 * c_ln + r1 * pc;
        h_new[idx] = h2;
        split1(h2, hh, hl, idx);
    }
}

// ---------------------------------------------------------------------------
// Launch
// ---------------------------------------------------------------------------
static inline float* fsym(const void* s) { void* p = nullptr; cudaGetSymbolAddress(&p, s); return (float*)p; }
static inline bf16*  bsym(const void* s) { void* p = nullptr; cudaGetSymbolAddress(&p, s); return (bf16*)p; }

extern "C" void kernel_launch(void* const* d_in, const int* in_sizes, int n_in,
                              void* d_out, int out_size)
{
    const float* x     = (const float*)d_in[0];
    const float* xs    = (const float*)d_in[1];
    const float* W_p   = (const float*)d_in[2];
    const float* b_p   = (const float*)d_in[3];
    const float* g_p   = (const float*)d_in[4];
    const float* be_p  = (const float*)d_in[5];
    const float* W_s   = (const float*)d_in[6];
    const float* b_s   = (const float*)d_in[7];
    const float* g_s   = (const float*)d_in[8];
    const float* be_s  = (const float*)d_in[9];
    const float* Wih_l = (const float*)d_in[10];
    const float* Whh_l = (const float*)d_in[11];
    const float* bih_l = (const float*)d_in[12];
    const float* bhh_l = (const float*)d_in[13];
    const float* Wih_s = (const float*)d_in[14];
    const float* Whh_s = (const float*)d_in[15];
    const float* bih_s = (const float*)d_in[16];
    const float* bhh_s = (const float*)d_in[17];
    const float* W_g   = (const float*)d_in[18];
    const float* b_g   = (const float*)d_in[19];
    const float* W_c   = (const float*)d_in[20];
    const float* b_c   = (const float*)d_in[21];

    float* out = (float*)d_out;
    float* out_logits = out;
    float* out_r      = out + BB * NCLS;

    bf16 *xh = bsym(g_x_hi), *xl = bsym(g_x_lo);
    bf16 *xsh = bsym(g_xs_hi), *xsl = bsym(g_xs_lo);
    bf16 *fh = bsym(g_f_hi), *fl = bsym(g_f_lo);
    bf16 *sfh = bsym(g_sf_hi), *sfl = bsym(g_sf_lo);
    bf16 *Wph = bsym(g_Wp_hi), *Wpl = bsym(g_Wp_lo);
    bf16 *Wsh = bsym(g_Ws_hi), *Wsl = bsym(g_Ws_lo);
    bf16 *Wlh = bsym(g_Wl_hi), *Wll = bsym(g_Wl_lo);
    bf16 *Whlh = bsym(g_Whl_hi), *Whll = bsym(g_Whl_lo);
    bf16 *Wish = bsym(g_Wis_hi), *Wisl = bsym(g_Wis_lo);
    bf16 *Whsh = bsym(g_Whs_hi), *Whsl = bsym(g_Whs_lo);
    bf16 *Wch = bsym(g_Wc_hi), *Wcl = bsym(g_Wc_lo);

    float* sfeats = fsym(g_sfeats);
    float* sgpre  = fsym(g_sgpre);
    float* lgpre  = fsym(g_lgpre);
    float* Gs  = fsym(g_Gs);
    float* GlA = fsym(g_GlA);
    float* GlB = fsym(g_GlB);
    float* hl = fsym(g_hl);
    float* cl = fsym(g_cl);
    float* hs = fsym(g_hs);
    float* cs = fsym(g_cs);
    bf16* hlh = bsym(g_hl_hi); bf16* hll = bsym(g_hl_lo);
    bf16* hsh = bsym(g_hs_hi); bf16* hsl = bsym(g_hs_lo);

    cudaFuncSetAttribute(gemm3_kernel, cudaFuncAttributeMaxDynamicSharedMemorySize, GSMEM);
    cudaFuncSetAttribute(step_gemm_kernel, cudaFuncAttributeMaxDynamicSharedMemorySize, GSMEM);

    const int TPB = 256;

    // ---- fused split of all inputs & weights into bf16 pairs
    {
        SJobs jb;
        const float* srcs[9] = { x, xs, W_p, W_s, Wih_l, Whh_l, Wih_s, Whh_s, W_c };
        bf16* his[9] = { xh, xsh, Wph, Wsh, Wlh, Whlh, Wish, Whsh, Wch };
        bf16* los[9] = { xl, xsl, Wpl, Wsl, Wll, Whll, Wisl, Whsl, Wcl };
        long  ns [9] = { (long)MBT * 2048, (long)MBT * 1280, 2048L * 2048, 512L * 1280,
                         4096L * 2560, 4096L * 1024, 2048L * 512, 2048L * 512,
                         (long)NCLS * 1024 };
        unsigned cum = 0;
        for (int k = 0; k < 9; k++) {
            jb.j[k].src = (const float4*)srcs[k];
            jb.j[k].hi  = (__nv_bfloat162*)his[k];
            jb.j[k].lo  = (__nv_bfloat162*)los[k];
            jb.cum[k] = cum;
            cum += (unsigned)(ns[k] / 4);
        }
        jb.cum[9] = cum;
        int grid = (int)((cum / 2 + TPB - 1) / TPB);     // 2 float4 per thread
        split_all_kernel<<<grid, TPB>>>(jb, cum);
    }
    zero_states_kernel<<<(BB * LL + 255) / 256, TPB>>>(hl, cl, hs, cs, hlh, hll, hsh, hsl);

    // ---- Phase 1: time-parallel GEMMs
    // feats(split) = relu(BN(x @ W_p^T + b_p))
    gemm3_kernel<<<dim3(2048 / 128, MBT / 128), 512, GSMEM>>>(
        xh, xl, 2048, nullptr, nullptr, 0, 2048,
        Wph, Wpl, 2048, 2048, 2048,
        b_p, nullptr, nullptr, 0, g_p, be_p,
        nullptr, 0, fh, fl, 2048);
    // sfeats(fp32+split) = relu(BN(xs @ W_s^T + b_s))
    gemm3_kernel<<<dim3(512 / 128, MBT / 128), 512, GSMEM>>>(
        xsh, xsl, 1280, nullptr, nullptr, 0, 1280,
        Wsh, Wsl, 1280, 512, 1280,
        b_s, nullptr, nullptr, 0, g_s, be_s,
        sfeats, 512, sfh, sfl, 512);
    // sgpre = sfeats @ Wih_s^T + bih_s + bhh_s
    gemm3_kernel<<<dim3(2048 / 128, MBT / 128), 512, GSMEM>>>(
        sfh, sfl, 512, nullptr, nullptr, 0, 512,
        Wish, Wisl, 512, 2048, 512,
        bih_s, bhh_s, nullptr, 0, nullptr, nullptr,
        sgpre, 2048, nullptr, nullptr, 0);
    // lgpre = [feats, sfeats] @ Wih_l^T + bih_l + bhh_l   (K-concat 2048+512)
    gemm3_kernel<<<dim3(4096 / 128, MBT / 128), 512, GSMEM>>>(
        fh, fl, 2048, sfh, sfl, 512, 2048,
        Wlh, Wll, 2560, 4096, 2560,
        bih_l, bhh_l, nullptr, 0, nullptr, nullptr,
        lgpre, 4096, nullptr, nullptr, 0);

    // ---- Phase 2: recurrence (2 launches per step)
    for (int t = 0; t < TT; t++) {
        int cur = t & 1, nxt = 1 - cur;
        float* hl_c = hl + (size_t)cur * BB * LL;
        float* cl_c = cl + (size_t)cur * BB * LL;
        float* hl_n = hl + (size_t)nxt * BB * LL;
        float* cl_n = cl + (size_t)nxt * BB * LL;
        float* cs_c = cs + (size_t)cur * BB * SS;
        float* hs_n = hs + (size_t)nxt * BB * SS;
        float* cs_n = cs + (size_t)nxt * BB * SS;
        bf16* hlh_c = hlh + (size_t)cur * BB * LL;
        bf16* hll_c = hll + (size_t)cur * BB * LL;
        bf16* hlh_n = hlh + (size_t)nxt * BB * LL;
        bf16* hll_n = hll + (size_t)nxt * BB * LL;
        bf16* hsh_c = hsh + (size_t)cur * BB * SS;
        bf16* hsl_c = hsl + (size_t)cur * BB * SS;
        bf16* hsh_n = hsh + (size_t)nxt * BB * SS;
        bf16* hsl_n = hsl + (size_t)nxt * BB * SS;
        float* r_t = out_r + (size_t)t * BB * 2;

        step_gemm_kernel<<<dim3(4096 / 128, BB / 128, 3), 512, GSMEM>>>(
            hsh_c, hsl_c, Whsh, Whsl, sgpre + (size_t)t * 2048,
            hlh_c, hll_c, Whlh, Whll, lgpre + (size_t)t * 4096,
            Gs, GlA, GlB);
        step_post_kernel<<<BB, 256>>>(
            Gs, GlA, GlB, sfeats, t, hl_c, cl_c, cs_c,
            hs_n, cs_n, hsh_n, hsl_n,
            W_g, b_g, r_t, hl_n, cl_n, hlh_n, hll_n);
    }

    // ---- classifier on final h_l (buffer 0 after 64 steps)
    gemm3_kernel<<<dim3((NCLS + 127) / 128, BB / 128), 512, GSMEM>>>(
        hlh, hll, 1024, nullptr, nullptr, 0, 1024,
        Wch, Wcl, 1024, NCLS, 1024,
        b_c, nullptr, nullptr, 0, nullptr, nullptr,
        out_logits, NCLS, nullptr, nullptr, 0);
}